// round 2
// baseline (speedup 1.0000x reference)
#include <cuda_runtime.h>
#include <math.h>

#define TX 160
#define TY 40
#define BB 16
#define HH 256
#define CC 512
#define INDIM 128
#define VV 30000
#define G4 1024      // 4*H
#define FF 896       // H + C + IN

// ---------------- device scratch (static, no allocs) ----------------
__device__ float g_pctx[TX * BB * CC];          // 5.24 MB
__device__ float g_h[BB * HH];
__device__ float g_c[BB * HH];
__device__ float g_h1[BB * HH];
__device__ float g_c1[BB * HH];
__device__ float g_gates[BB * G4];
__device__ float g_hq[BB * CC];
__device__ float g_acc[BB * TX];
__device__ float g_sc[TX * BB];
__device__ float g_mx[BB];
__device__ float g_den[BB];
__device__ float g_atted[BB * CC];
__device__ float g_ifoc[BB * G4];
__device__ float g_feats[TY * BB * FF];         // 2.29 MB
__device__ float g_logits[TY * BB * VV];        // 76.8 MB
__device__ float g_cost[TY * BB];
__device__ float g_cov_sum;
__device__ unsigned g_bar;

// ---------------- helpers ----------------
__device__ __forceinline__ float sigf(float x) { return 1.0f / (1.0f + expf(-x)); }

__device__ __forceinline__ unsigned long long dup2(float a) {
    unsigned long long r;
    asm("mov.b64 %0, {%1, %1};" : "=l"(r) : "f"(a));
    return r;
}
__device__ __forceinline__ void ffma2(unsigned long long& d, unsigned long long a, unsigned long long b) {
    asm("fma.rn.f32x2 %0, %1, %2, %0;" : "+l"(d) : "l"(a), "l"(b));
}
__device__ __forceinline__ void unpack2(unsigned long long v, float& lo, float& hi) {
    asm("mov.b64 {%0, %1}, %2;" : "=f"(lo), "=f"(hi) : "l"(v));
}

// float4 dot with 4 accumulators (ILP)
__device__ __forceinline__ float dot_vec(const float* __restrict__ a, const float* __restrict__ b, int n4) {
    const float4* A = (const float4*)a;
    const float4* B = (const float4*)b;
    float s0 = 0.f, s1 = 0.f, s2 = 0.f, s3 = 0.f;
#pragma unroll 8
    for (int k = 0; k < n4; k++) {
        float4 x = A[k], y = B[k];
        s0 = fmaf(x.x, y.x, s0);
        s1 = fmaf(x.y, y.y, s1);
        s2 = fmaf(x.z, y.z, s2);
        s3 = fmaf(x.w, y.w, s3);
    }
    return (s0 + s1) + (s2 + s3);
}

// monotonic grid barrier (all gridDim.x blocks must be co-resident)
__device__ __forceinline__ void grid_sync(unsigned& epoch) {
    __syncthreads();
    if (threadIdx.x == 0) {
        __threadfence();
        epoch += gridDim.x;
        atomicAdd(&g_bar, 1u);
        while (*((volatile unsigned*)&g_bar) < epoch) { __nanosleep(64); }
        __threadfence();
    }
    __syncthreads();
}

// ---------------- init ----------------
__global__ void init_kernel(const float* __restrict__ h0, const float* __restrict__ c0,
                            const float* __restrict__ cov0) {
    int tid = threadIdx.x;
    if (tid == 0) { g_bar = 0u; g_cov_sum = 0.f; }
    for (int i = tid; i < BB * HH; i += blockDim.x) { g_h[i] = h0[i]; g_c[i] = c0[i]; }
    for (int i = tid; i < BB * TX; i += blockDim.x) { g_acc[i] = cov0[i]; }
}

// ---------------- generic C = A @ B^T + bias GEMM (f32x2 inner) ----------------
// A: [M,K] row-major, Bm: [N,K] row-major, Cout: [M,N]. M%64==0, K%16==0. N guarded.
#define BMg 64
#define BNg 128
#define BKg 16
#define ASTR 68     // padded stride (16B-aligned rows: 68*4=272=16*17)
#define BSTR 130

__global__ __launch_bounds__(256) void gemm_abT_bias(
    const float* __restrict__ A, const float* __restrict__ Bm,
    const float* __restrict__ bias, float* __restrict__ Cout,
    int M, int N, int K)
{
    __shared__ __align__(16) float As[BKg * ASTR];
    __shared__ __align__(16) float Bs[BKg * BSTR];

    const int tid = threadIdx.x;
    const int tx = tid & 15;   // col group: 8 cols each
    const int ty = tid >> 4;   // row group: 4 rows each
    const int m0 = blockIdx.y * BMg;
    const int n0 = blockIdx.x * BNg;

    const int a_m = tid >> 2;      // 0..63
    const int a_kq = tid & 3;      // 0..3

    unsigned long long acc[4][4];
#pragma unroll
    for (int i = 0; i < 4; i++)
#pragma unroll
        for (int j = 0; j < 4; j++) acc[i][j] = 0ull;

    for (int k0 = 0; k0 < K; k0 += BKg) {
        // load A tile (transposed: As[k][m])
        {
            float4 av = *(const float4*)(A + (size_t)(m0 + a_m) * K + k0 + a_kq * 4);
            As[(a_kq * 4 + 0) * ASTR + a_m] = av.x;
            As[(a_kq * 4 + 1) * ASTR + a_m] = av.y;
            As[(a_kq * 4 + 2) * ASTR + a_m] = av.z;
            As[(a_kq * 4 + 3) * ASTR + a_m] = av.w;
        }
        // load B tile (transposed: Bs[k][n])
#pragma unroll
        for (int i = 0; i < 2; i++) {
            int f = tid + i * 256;
            int n = f >> 2;
            int kq = f & 3;
            int gn = n0 + n;
            float4 bv = make_float4(0.f, 0.f, 0.f, 0.f);
            if (gn < N) bv = *(const float4*)(Bm + (size_t)gn * K + k0 + kq * 4);
            Bs[(kq * 4 + 0) * BSTR + n] = bv.x;
            Bs[(kq * 4 + 1) * BSTR + n] = bv.y;
            Bs[(kq * 4 + 2) * BSTR + n] = bv.z;
            Bs[(kq * 4 + 3) * BSTR + n] = bv.w;
        }
        __syncthreads();
#pragma unroll
        for (int k = 0; k < BKg; k++) {
            float4 a4 = *(const float4*)&As[k * ASTR + ty * 4];
            unsigned long long a2[4];
            a2[0] = dup2(a4.x); a2[1] = dup2(a4.y); a2[2] = dup2(a4.z); a2[3] = dup2(a4.w);
            const unsigned long long* bp = (const unsigned long long*)&Bs[k * BSTR + tx * 8];
            unsigned long long b0 = bp[0], b1 = bp[1], b2 = bp[2], b3 = bp[3];
#pragma unroll
            for (int i = 0; i < 4; i++) {
                ffma2(acc[i][0], a2[i], b0);
                ffma2(acc[i][1], a2[i], b1);
                ffma2(acc[i][2], a2[i], b2);
                ffma2(acc[i][3], a2[i], b3);
            }
        }
        __syncthreads();
    }
    // store
#pragma unroll
    for (int i = 0; i < 4; i++) {
        int m = m0 + ty * 4 + i;
#pragma unroll
        for (int j = 0; j < 4; j++) {
            int n = n0 + tx * 8 + j * 2;
            float lo, hi;
            unpack2(acc[i][j], lo, hi);
            if (n < N)     Cout[(size_t)m * N + n]     = lo + bias[n];
            if (n + 1 < N) Cout[(size_t)m * N + n + 1] = hi + bias[n + 1];
        }
    }
}

// ---------------- persistent recurrence ----------------
#define NBLK 128
__global__ __launch_bounds__(256) void decoder_kernel(
    const float* __restrict__ y_emb, const float* __restrict__ context,
    const float* __restrict__ x_mask, const float* __restrict__ y_mask,
    const float* __restrict__ W_ih, const float* __restrict__ W_hh,
    const float* __restrict__ b_ih, const float* __restrict__ b_hh,
    const float* __restrict__ Wx, const float* __restrict__ Ux, const float* __restrict__ bx,
    const float* __restrict__ W_comb, const float* __restrict__ U_att,
    const float* __restrict__ W_cov)
{
    const int NT = gridDim.x * blockDim.x;
    const int gtid = blockIdx.x * blockDim.x + threadIdx.x;
    const int lane = gtid & 31;
    const int wid = gtid >> 5;
    const int nwarps = NT >> 5;
    unsigned epoch = 0;

    for (int t = 0; t < TY; t++) {
        const float* yrow_base = y_emb + (size_t)t * BB * INDIM;

        // ---- P1: gates = y_t @ W_ih^T + h @ W_hh^T + (b_ih+b_hh) ----
        for (int idx = gtid; idx < BB * G4; idx += NT) {
            int b = idx >> 10, j = idx & 1023;
            float s = b_ih[j] + b_hh[j];
            s += dot_vec(yrow_base + b * INDIM, W_ih + (size_t)j * INDIM, INDIM / 4);
            s += dot_vec(g_h + b * HH, W_hh + (size_t)j * HH, HH / 4);
            g_gates[idx] = s;
        }
        grid_sync(epoch);

        // ---- P2: LSTM cell 1 (+ y_mask) ----
        for (int idx = gtid; idx < BB * HH; idx += NT) {
            int b = idx >> 8, u = idx & 255;
            int base = b * G4 + u;
            float gi = g_gates[base], gf = g_gates[base + HH];
            float gg = g_gates[base + 2 * HH], go = g_gates[base + 3 * HH];
            float c_old = g_c[idx], h_old = g_h[idx];
            float c1 = sigf(gf) * c_old + sigf(gi) * tanhf(gg);
            float h1 = sigf(go) * tanhf(c1);
            float ym = y_mask[t * BB + b];
            g_h1[idx] = ym * h1 + (1.f - ym) * h_old;
            g_c1[idx] = ym * c1 + (1.f - ym) * c_old;
        }
        grid_sync(epoch);

        // ---- P3: hq = [h1;c1] @ W_comb^T ----
        for (int idx = gtid; idx < BB * CC; idx += NT) {
            int b = idx >> 9, o = idx & 511;
            const float* wr = W_comb + (size_t)o * (2 * HH);
            float s = dot_vec(g_h1 + b * HH, wr, HH / 4)
                    + dot_vec(g_c1 + b * HH, wr + HH, HH / 4);
            g_hq[idx] = s;
        }
        grid_sync(epoch);

        // ---- P4: attention scores sc[x,b] (warp per (x,b)) ----
        for (int p = wid; p < TX * BB; p += nwarps) {
            int x = p >> 4, b = p & 15;
            float accv = g_acc[b * TX + x];
            const float* pc = g_pctx + (size_t)p * CC;
            const float* hqb = g_hq + b * CC;
            float s = 0.f;
            for (int c = lane; c < CC; c += 32)
                s += tanhf(pc[c] + hqb[c] + accv * W_cov[c]) * U_att[c];
#pragma unroll
            for (int o = 16; o > 0; o >>= 1) s += __shfl_xor_sync(0xffffffffu, s, o);
            if (lane == 0) g_sc[p] = x_mask[p] * s;
        }
        grid_sync(epoch);

        // ---- P5a: per-batch max & denom ----
        if (wid < BB) {
            int b = wid;
            float mx = -3.4e38f;
            for (int x = lane; x < TX; x += 32) mx = fmaxf(mx, g_sc[x * BB + b]);
#pragma unroll
            for (int o = 16; o > 0; o >>= 1) mx = fmaxf(mx, __shfl_xor_sync(0xffffffffu, mx, o));
            float sm = 0.f;
            for (int x = lane; x < TX; x += 32)
                sm += expf(g_sc[x * BB + b] - mx) * x_mask[x * BB + b];
#pragma unroll
            for (int o = 16; o > 0; o >>= 1) sm += __shfl_xor_sync(0xffffffffu, sm, o);
            if (lane == 0) { g_mx[b] = mx; g_den[b] = sm; }
        }
        grid_sync(epoch);

        // ---- P5b: atted + coverage update (parallel jobs) ----
        for (int idx = gtid; idx < BB * CC + TX * BB; idx += NT) {
            if (idx < BB * CC) {
                int b = idx >> 9, c = idx & 511;
                float mx = g_mx[b], inv = 1.f / g_den[b];
                float s = 0.f;
                for (int x = 0; x < TX; x++) {
                    int p = x * BB + b;
                    float e = expf(g_sc[p] - mx) * x_mask[p];
                    s = fmaf(e, context[(size_t)p * CC + c], s);
                }
                g_atted[idx] = s * inv;
            } else {
                int p = idx - BB * CC;
                int x = p >> 4, b = p & 15;
                float w = expf(g_sc[p] - g_mx[b]) * x_mask[p] / g_den[b];
                float old = g_acc[b * TX + x];
                float cmin = fminf(w, old);
                g_acc[b * TX + x] = old + w;
#pragma unroll
                for (int o = 16; o > 0; o >>= 1) cmin += __shfl_xor_sync(0xffffffffu, cmin, o);
                if (lane == 0) atomicAdd(&g_cov_sum, cmin);
            }
        }
        grid_sync(epoch);

        // ---- P6: ifoc = h1 @ Ux^T + atted @ Wx^T + bx ----
        for (int idx = gtid; idx < BB * G4; idx += NT) {
            int b = idx >> 10, j = idx & 1023;
            float s = bx[j];
            s += dot_vec(g_h1 + b * HH, Ux + (size_t)j * HH, HH / 4);
            s += dot_vec(g_atted + b * CC, Wx + (size_t)j * CC, CC / 4);
            g_ifoc[idx] = s;
        }
        grid_sync(epoch);

        // ---- P7: LSTM cell 2 + write feats ----
        for (int idx = gtid; idx < BB * (HH + CC + INDIM); idx += NT) {
            if (idx < BB * HH) {
                int b = idx >> 8, u = idx & 255;
                int base = b * G4 + u;
                float i2 = g_ifoc[base], f2 = g_ifoc[base + HH];
                float o2 = g_ifoc[base + 2 * HH], g2 = g_ifoc[base + 3 * HH];
                float c1 = g_c1[idx], h1 = g_h1[idx];
                float c2 = sigf(f2) * c1 + sigf(i2) * tanhf(g2);
                float h2 = sigf(o2) * tanhf(c2);
                float ym = y_mask[t * BB + b];
                c2 = ym * c2 + (1.f - ym) * c1;
                h2 = ym * h2 + (1.f - ym) * h1;
                g_h[idx] = h2;
                g_c[idx] = c2;
                g_feats[(size_t)(t * BB + b) * FF + u] = h2;
            } else if (idx < BB * (HH + CC)) {
                int q = idx - BB * HH;
                int b = q >> 9, c = q & 511;
                g_feats[(size_t)(t * BB + b) * FF + HH + c] = g_atted[q];
            } else {
                int q = idx - BB * (HH + CC);
                int b = q >> 7, k = q & 127;
                g_feats[(size_t)(t * BB + b) * FF + HH + CC + k] = yrow_base[b * INDIM + k];
            }
        }
        grid_sync(epoch);
    }
}

// ---------------- softmax / cost per row ----------------
__global__ __launch_bounds__(256) void softmax_cost_kernel(const int* __restrict__ y_idx,
                                                           float* __restrict__ out) {
    __shared__ float sred[256];
    __shared__ float s_mx, s_sum;
    const int m = blockIdx.x;
    const int tid = threadIdx.x;
    const float* row = g_logits + (size_t)m * VV;

    float mx = -3.4e38f;
    for (int v = tid; v < VV; v += 256) mx = fmaxf(mx, row[v]);
    sred[tid] = mx; __syncthreads();
    for (int s = 128; s > 0; s >>= 1) {
        if (tid < s) sred[tid] = fmaxf(sred[tid], sred[tid + s]);
        __syncthreads();
    }
    if (tid == 0) s_mx = sred[0];
    __syncthreads();
    mx = s_mx;

    float sm = 0.f;
    for (int v = tid; v < VV; v += 256) sm += expf(row[v] - mx);
    sred[tid] = sm; __syncthreads();
    for (int s = 128; s > 0; s >>= 1) {
        if (tid < s) sred[tid] += sred[tid + s];
        __syncthreads();
    }
    if (tid == 0) {
        s_sum = sred[0];
        float lz = mx + logf(sred[0]);
        g_cost[m] = lz - row[y_idx[m]];
    }
    __syncthreads();

    if (m >= (TY - 1) * BB) {
        int b = m - (TY - 1) * BB;
        float inv = 1.f / s_sum;
        for (int v = tid; v < VV; v += 256)
            out[(size_t)b * VV + v] = expf(row[v] - mx) * inv;
    }
}

// ---------------- final scalars ----------------
__global__ void finalize_kernel(const float* __restrict__ y_mask, float* __restrict__ out) {
    int b = threadIdx.x;
    float cb = 0.f;
    if (b < BB) {
        float num = 0.f, den = 0.f;
        for (int t = 0; t < TY; t++) {
            float ym = y_mask[t * BB + b];
            num += g_cost[t * BB + b] * ym;
            den += ym;
        }
        cb = num / den;
    }
#pragma unroll
    for (int o = 16; o > 0; o >>= 1) cb += __shfl_xor_sync(0xffffffffu, cb, o);
    if (threadIdx.x == 0) {
        out[(size_t)BB * VV]     = cb / (float)BB;
        out[(size_t)BB * VV + 1] = g_cov_sum / (float)(TY * BB);
    }
}

// ---------------- launch ----------------
extern "C" void kernel_launch(void* const* d_in, const int* in_sizes, int n_in,
                              void* d_out, int out_size) {
    const float* y_emb   = (const float*)d_in[0];
    const float* context = (const float*)d_in[1];
    const float* h0      = (const float*)d_in[2];
    const float* c0      = (const float*)d_in[3];
    const float* x_mask  = (const float*)d_in[4];
    const float* y_mask  = (const float*)d_in[5];
    const float* cov0    = (const float*)d_in[6];
    const int*   y_idx   = (const int*)d_in[7];
    const float* W_ih    = (const float*)d_in[8];
    const float* W_hh    = (const float*)d_in[9];
    const float* b_ih    = (const float*)d_in[10];
    const float* b_hh    = (const float*)d_in[11];
    const float* Wx      = (const float*)d_in[12];
    const float* Ux      = (const float*)d_in[13];
    const float* bx      = (const float*)d_in[14];
    const float* Wc_att  = (const float*)d_in[15];
    const float* b_att   = (const float*)d_in[16];
    const float* W_comb  = (const float*)d_in[17];
    const float* U_att   = (const float*)d_in[18];
    const float* W_cov   = (const float*)d_in[19];
    const float* Wp      = (const float*)d_in[20];
    const float* bp      = (const float*)d_in[21];
    float* out = (float*)d_out;

    void *p_pctx, *p_feats, *p_logits;
    cudaGetSymbolAddress(&p_pctx, g_pctx);
    cudaGetSymbolAddress(&p_feats, g_feats);
    cudaGetSymbolAddress(&p_logits, g_logits);

    init_kernel<<<1, 256>>>(h0, c0, cov0);

    // pctx = context @ Wc_att^T + b_att : M=2560, N=512, K=512
    {
        dim3 grid(CC / BNg, (TX * BB) / BMg);   // (4, 40)
        gemm_abT_bias<<<grid, 256>>>(context, Wc_att, b_att, (float*)p_pctx,
                                     TX * BB, CC, CC);
    }

    decoder_kernel<<<NBLK, 256>>>(y_emb, context, x_mask, y_mask,
                                  W_ih, W_hh, b_ih, b_hh, Wx, Ux, bx,
                                  W_comb, U_att, W_cov);

    // logits = feats @ Wp^T + bp : M=640, N=30000, K=896
    {
        dim3 grid((VV + BNg - 1) / BNg, (TY * BB) / BMg);   // (235, 10)
        gemm_abT_bias<<<grid, 256>>>((const float*)p_feats, Wp, bp, (float*)p_logits,
                                     TY * BB, VV, FF);
    }

    softmax_cost_kernel<<<TY * BB, 256>>>(y_idx, out);
    finalize_kernel<<<1, 32>>>(y_mask, out);
}

// round 3
// speedup vs baseline: 1.0201x; 1.0201x over previous
#include <cuda_runtime.h>
#include <math.h>

#define TX 160
#define TY 40
#define BB 16
#define HH 256
#define CC 512
#define INDIM 128
#define VV 30000
#define G4 1024      // 4*H
#define FF 896       // H + C + IN

// ---------------- device scratch (static, no allocs) ----------------
__device__ __align__(256) float g_pctx[TX * BB * CC];          // 5.24 MB
__device__ __align__(256) float g_h[BB * HH];
__device__ __align__(256) float g_c[BB * HH];
__device__ __align__(256) float g_gates[BB * G4];
__device__ __align__(256) float g_hq[BB * CC];
__device__ __align__(256) float g_acc[BB * TX];
__device__ __align__(256) float g_sc[TX * BB];
__device__ __align__(256) float g_atted[BB * CC];
__device__ __align__(256) float g_ifoc[BB * G4];
__device__ __align__(256) float g_feats[TY * BB * FF];         // 2.29 MB
__device__ __align__(256) float g_logits[TY * BB * VV];        // 76.8 MB
__device__ __align__(256) float g_cost[TY * BB];
__device__ float g_cov_sum;
__device__ unsigned g_bar;

// ---------------- helpers ----------------
__device__ __forceinline__ float tanh_fast(float x) {
    float y;
    asm("tanh.approx.f32 %0, %1;" : "=f"(y) : "f"(x));
    return y;
}
__device__ __forceinline__ float sig_fast(float x) {
    return fmaf(tanh_fast(0.5f * x), 0.5f, 0.5f);
}

__device__ __forceinline__ unsigned long long dup2(float a) {
    unsigned long long r;
    asm("mov.b64 %0, {%1, %1};" : "=l"(r) : "f"(a));
    return r;
}
__device__ __forceinline__ void ffma2(unsigned long long& d, unsigned long long a, unsigned long long b) {
    asm("fma.rn.f32x2 %0, %1, %2, %0;" : "+l"(d) : "l"(a), "l"(b));
}
__device__ __forceinline__ void unpack2(unsigned long long v, float& lo, float& hi) {
    asm("mov.b64 {%0, %1}, %2;" : "=f"(lo), "=f"(hi) : "l"(v));
}

// float4 dot with 4 accumulators (ILP)
__device__ __forceinline__ float dot_vec(const float* a, const float* b, int n4) {
    const float4* A = (const float4*)a;
    const float4* B = (const float4*)b;
    float s0 = 0.f, s1 = 0.f, s2 = 0.f, s3 = 0.f;
#pragma unroll 8
    for (int k = 0; k < n4; k++) {
        float4 x = A[k], y = B[k];
        s0 = fmaf(x.x, y.x, s0);
        s1 = fmaf(x.y, y.y, s1);
        s2 = fmaf(x.z, y.z, s2);
        s3 = fmaf(x.w, y.w, s3);
    }
    return (s0 + s1) + (s2 + s3);
}

// monotonic grid barrier (all gridDim.x blocks must be co-resident)
__device__ __forceinline__ void grid_sync(unsigned& epoch) {
    __syncthreads();
    if (threadIdx.x == 0) {
        __threadfence();
        epoch += gridDim.x;
        atomicAdd(&g_bar, 1u);
        while (*((volatile unsigned*)&g_bar) < epoch) { __nanosleep(64); }
        __threadfence();
    }
    __syncthreads();
}

// ---------------- init ----------------
__global__ void init_kernel(const float* __restrict__ h0, const float* __restrict__ c0,
                            const float* __restrict__ cov0) {
    int tid = threadIdx.x;
    if (tid == 0) { g_bar = 0u; g_cov_sum = 0.f; }
    for (int i = tid; i < BB * HH; i += blockDim.x) { g_h[i] = h0[i]; g_c[i] = c0[i]; }
    for (int i = tid; i < BB * TX; i += blockDim.x) { g_acc[i] = cov0[i]; }
}

// ---------------- GEMM: C = A @ B^T + bias, 128x128 tile, 8x8/thread, f32x2 ----
// A: [M,K] row-major (M%128==0, K%16==0), Bm: [N,K] row-major (N guarded).
#define BMg 128
#define BNg 128
#define BKg 16
#define TSTR 132   // padded stride, 132*4B = 16B multiple

__global__ __launch_bounds__(256, 2) void gemm_abT_bias(
    const float* __restrict__ A, const float* __restrict__ Bm,
    const float* __restrict__ bias, float* __restrict__ Cout,
    int M, int N, int K)
{
    __shared__ __align__(16) float As[BKg * TSTR];
    __shared__ __align__(16) float Bs[BKg * TSTR];

    const int tid = threadIdx.x;
    const int tx = tid & 15;   // 8 cols each
    const int ty = tid >> 4;   // 8 rows each
    const int m0 = blockIdx.x * BMg;
    const int n0 = blockIdx.y * BNg;

    unsigned long long acc[8][4];
#pragma unroll
    for (int i = 0; i < 8; i++)
#pragma unroll
        for (int j = 0; j < 4; j++) acc[i][j] = 0ull;

    for (int k0 = 0; k0 < K; k0 += BKg) {
        // load tiles transposed: Xs[k][row]
#pragma unroll
        for (int i = 0; i < 2; i++) {
            int f = tid + i * 256;       // 0..511
            int row = f >> 2;            // 0..127
            int kq = f & 3;              // 0..3
            float4 av = *(const float4*)(A + (size_t)(m0 + row) * K + k0 + kq * 4);
            As[(kq * 4 + 0) * TSTR + row] = av.x;
            As[(kq * 4 + 1) * TSTR + row] = av.y;
            As[(kq * 4 + 2) * TSTR + row] = av.z;
            As[(kq * 4 + 3) * TSTR + row] = av.w;
            int gn = n0 + row;
            float4 bv = make_float4(0.f, 0.f, 0.f, 0.f);
            if (gn < N) bv = *(const float4*)(Bm + (size_t)gn * K + k0 + kq * 4);
            Bs[(kq * 4 + 0) * TSTR + row] = bv.x;
            Bs[(kq * 4 + 1) * TSTR + row] = bv.y;
            Bs[(kq * 4 + 2) * TSTR + row] = bv.z;
            Bs[(kq * 4 + 3) * TSTR + row] = bv.w;
        }
        __syncthreads();
#pragma unroll
        for (int k = 0; k < BKg; k++) {
            float4 a0 = *(const float4*)&As[k * TSTR + ty * 8];
            float4 a1 = *(const float4*)&As[k * TSTR + ty * 8 + 4];
            ulonglong2 bq0 = *(const ulonglong2*)&Bs[k * TSTR + tx * 8];
            ulonglong2 bq1 = *(const ulonglong2*)&Bs[k * TSTR + tx * 8 + 4];
            unsigned long long b0 = bq0.x, b1 = bq0.y, b2 = bq1.x, b3 = bq1.y;
            float af[8] = {a0.x, a0.y, a0.z, a0.w, a1.x, a1.y, a1.z, a1.w};
#pragma unroll
            for (int i = 0; i < 8; i++) {
                unsigned long long a2 = dup2(af[i]);
                ffma2(acc[i][0], a2, b0);
                ffma2(acc[i][1], a2, b1);
                ffma2(acc[i][2], a2, b2);
                ffma2(acc[i][3], a2, b3);
            }
        }
        __syncthreads();
    }
    // store
#pragma unroll
    for (int i = 0; i < 8; i++) {
        int m = m0 + ty * 8 + i;
#pragma unroll
        for (int j = 0; j < 4; j++) {
            int n = n0 + tx * 8 + j * 2;
            float lo, hi;
            unpack2(acc[i][j], lo, hi);
            if (n < N)     Cout[(size_t)m * N + n]     = lo + bias[n];
            if (n + 1 < N) Cout[(size_t)m * N + n + 1] = hi + bias[n + 1];
        }
    }
}

// ---------------- persistent recurrence ----------------
#define NBLK 128
#define NTHR 320
__global__ __launch_bounds__(NTHR) void decoder_kernel(
    const float* __restrict__ y_emb, const float* __restrict__ context,
    const float* __restrict__ x_mask, const float* __restrict__ y_mask,
    const float* __restrict__ W_ih, const float* __restrict__ W_hh,
    const float* __restrict__ b_ih, const float* __restrict__ b_hh,
    const float* __restrict__ Wx, const float* __restrict__ Ux, const float* __restrict__ bx,
    const float* __restrict__ W_comb, const float* __restrict__ U_att,
    const float* __restrict__ W_cov)
{
    __shared__ __align__(16) float sh_h1[BB * HH];
    __shared__ __align__(16) float sh_c1[BB * HH];
    __shared__ __align__(16) float sh_watt[TX * BB];
    __shared__ float sh_mx[BB], sh_den[BB];

    const int NT = gridDim.x * blockDim.x;
    const int tid = threadIdx.x;
    const int gtid = blockIdx.x * blockDim.x + tid;
    const int lane = tid & 31;
    const int lwid = tid >> 5;                 // 0..9
    const int gwid = gtid >> 5;
    const int nwarps = NT >> 5;                // 1280
    unsigned epoch = 0;

    for (int t = 0; t < TY; t++) {
        const float* yrow_base = y_emb + (size_t)t * BB * INDIM;

        // ---- P1: gates = y_t @ W_ih^T + h @ W_hh^T + (b_ih+b_hh) ----
        for (int idx = gtid; idx < BB * G4; idx += NT) {
            int b = idx >> 10, j = idx & 1023;
            float s = b_ih[j] + b_hh[j];
            s += dot_vec(yrow_base + b * INDIM, W_ih + (size_t)j * INDIM, INDIM / 4);
            s += dot_vec(g_h + b * HH, W_hh + (size_t)j * HH, HH / 4);
            g_gates[idx] = s;
        }
        grid_sync(epoch);

        // ---- P2': LSTM cell 1 computed redundantly per block into smem ----
        for (int idx = tid; idx < BB * HH; idx += NTHR) {
            int b = idx >> 8, u = idx & 255;
            int base = b * G4 + u;
            float gi = g_gates[base], gf = g_gates[base + HH];
            float gg = g_gates[base + 2 * HH], go = g_gates[base + 3 * HH];
            float c_old = g_c[idx], h_old = g_h[idx];
            float c1 = sig_fast(gf) * c_old + sig_fast(gi) * tanh_fast(gg);
            float h1 = sig_fast(go) * tanh_fast(c1);
            float ym = y_mask[t * BB + b];
            sh_h1[idx] = ym * h1 + (1.f - ym) * h_old;
            sh_c1[idx] = ym * c1 + (1.f - ym) * c_old;
        }
        __syncthreads();

        // ---- P3: hq = [h1;c1] @ W_comb^T (h1/c1 from smem) ----
        for (int idx = gtid; idx < BB * CC; idx += NT) {
            int b = idx >> 9, o = idx & 511;
            const float* wr = W_comb + (size_t)o * (2 * HH);
            float s = dot_vec(sh_h1 + b * HH, wr, HH / 4)
                    + dot_vec(sh_c1 + b * HH, wr + HH, HH / 4);
            g_hq[idx] = s;
        }
        grid_sync(epoch);

        // ---- P4: attention scores sc[x,b] (warp per (x,b), 2 rounds exact) ----
        for (int p = gwid; p < TX * BB; p += nwarps) {
            int x = p >> 4, b = p & 15;
            float accv = g_acc[b * TX + x];
            const float* pc = g_pctx + (size_t)p * CC;
            const float* hqb = g_hq + b * CC;
            float s = 0.f;
#pragma unroll 4
            for (int c = lane; c < CC; c += 32)
                s += tanh_fast(fmaf(accv, W_cov[c], pc[c] + hqb[c])) * U_att[c];
#pragma unroll
            for (int o = 16; o > 0; o >>= 1) s += __shfl_xor_sync(0xffffffffu, s, o);
            if (lane == 0) g_sc[p] = x_mask[p] * s;
        }
        grid_sync(epoch);

        // ---- P5a': per-block softmax weights into smem (redundant) ----
        for (int b = lwid; b < BB; b += (NTHR >> 5)) {
            float mx = -3.4e38f;
            for (int x = lane; x < TX; x += 32) mx = fmaxf(mx, g_sc[x * BB + b]);
#pragma unroll
            for (int o = 16; o > 0; o >>= 1) mx = fmaxf(mx, __shfl_xor_sync(0xffffffffu, mx, o));
            float sm = 0.f;
            for (int x = lane; x < TX; x += 32) {
                float e = __expf(g_sc[x * BB + b] - mx) * x_mask[x * BB + b];
                sh_watt[x * BB + b] = e;
                sm += e;
            }
#pragma unroll
            for (int o = 16; o > 0; o >>= 1) sm += __shfl_xor_sync(0xffffffffu, sm, o);
            float inv = __fdividef(1.f, sm);
            for (int x = lane; x < TX; x += 32) sh_watt[x * BB + b] *= inv;
        }
        __syncthreads();

        // ---- P5b: atted (global split) + coverage (block 0) ----
        for (int idx = gtid; idx < BB * CC; idx += NT) {
            int b = idx >> 9, c = idx & 511;
            float s = 0.f;
#pragma unroll 4
            for (int x = 0; x < TX; x++) {
                int p = x * BB + b;
                s = fmaf(sh_watt[p], context[(size_t)p * CC + c], s);
            }
            g_atted[idx] = s;
        }
        if (blockIdx.x == 0) {
            float part = 0.f;
            for (int p = tid; p < TX * BB; p += NTHR) {
                int x = p >> 4, b = p & 15;
                float w = sh_watt[p];
                float old = g_acc[b * TX + x];
                part += fminf(w, old);
                g_acc[b * TX + x] = old + w;
            }
#pragma unroll
            for (int o = 16; o > 0; o >>= 1) part += __shfl_xor_sync(0xffffffffu, part, o);
            if (lane == 0) atomicAdd(&g_cov_sum, part);
        }
        grid_sync(epoch);

        // ---- P6: ifoc = h1 @ Ux^T + atted @ Wx^T + bx ----
        for (int idx = gtid; idx < BB * G4; idx += NT) {
            int b = idx >> 10, j = idx & 1023;
            float s = bx[j];
            s += dot_vec(sh_h1 + b * HH, Ux + (size_t)j * HH, HH / 4);
            s += dot_vec(g_atted + b * CC, Wx + (size_t)j * CC, CC / 4);
            g_ifoc[idx] = s;
        }
        grid_sync(epoch);

        // ---- P7: LSTM cell 2 + write feats + update h/c ----
        for (int idx = gtid; idx < BB * FF; idx += NT) {
            if (idx < BB * HH) {
                int b = idx >> 8, u = idx & 255;
                int base = b * G4 + u;
                float i2 = g_ifoc[base], f2 = g_ifoc[base + HH];
                float o2 = g_ifoc[base + 2 * HH], g2 = g_ifoc[base + 3 * HH];
                float c1 = sh_c1[idx], h1 = sh_h1[idx];
                float c2 = sig_fast(f2) * c1 + sig_fast(i2) * tanh_fast(g2);
                float h2 = sig_fast(o2) * tanh_fast(c2);
                float ym = y_mask[t * BB + b];
                c2 = ym * c2 + (1.f - ym) * c1;
                h2 = ym * h2 + (1.f - ym) * h1;
                g_h[idx] = h2;
                g_c[idx] = c2;
                g_feats[(size_t)(t * BB + b) * FF + u] = h2;
            } else if (idx < BB * (HH + CC)) {
                int q = idx - BB * HH;
                int b = q >> 9, c = q & 511;
                g_feats[(size_t)(t * BB + b) * FF + HH + c] = g_atted[q];
            } else {
                int q = idx - BB * (HH + CC);
                int b = q >> 7, k = q & 127;
                g_feats[(size_t)(t * BB + b) * FF + HH + CC + k] = yrow_base[b * INDIM + k];
            }
        }
        grid_sync(epoch);
    }
}

// ---------------- softmax / cost per row ----------------
__global__ __launch_bounds__(256) void softmax_cost_kernel(const int* __restrict__ y_idx,
                                                           float* __restrict__ out) {
    __shared__ float sred[256];
    __shared__ float s_mx, s_sum;
    const int m = blockIdx.x;
    const int tid = threadIdx.x;
    const float* row = g_logits + (size_t)m * VV;

    float mx = -3.4e38f;
    for (int v = tid; v < VV; v += 256) mx = fmaxf(mx, row[v]);
    sred[tid] = mx; __syncthreads();
    for (int s = 128; s > 0; s >>= 1) {
        if (tid < s) sred[tid] = fmaxf(sred[tid], sred[tid + s]);
        __syncthreads();
    }
    if (tid == 0) s_mx = sred[0];
    __syncthreads();
    mx = s_mx;

    float sm = 0.f;
    for (int v = tid; v < VV; v += 256) sm += __expf(row[v] - mx);
    sred[tid] = sm; __syncthreads();
    for (int s = 128; s > 0; s >>= 1) {
        if (tid < s) sred[tid] += sred[tid + s];
        __syncthreads();
    }
    if (tid == 0) {
        s_sum = sred[0];
        float lz = mx + logf(sred[0]);
        g_cost[m] = lz - row[y_idx[m]];
    }
    __syncthreads();

    if (m >= (TY - 1) * BB) {
        int b = m - (TY - 1) * BB;
        float inv = __fdividef(1.f, s_sum);
        for (int v = tid; v < VV; v += 256)
            out[(size_t)b * VV + v] = __expf(row[v] - mx) * inv;
    }
}

// ---------------- final scalars ----------------
__global__ void finalize_kernel(const float* __restrict__ y_mask, float* __restrict__ out) {
    int b = threadIdx.x;
    float cb = 0.f;
    if (b < BB) {
        float num = 0.f, den = 0.f;
        for (int t = 0; t < TY; t++) {
            float ym = y_mask[t * BB + b];
            num += g_cost[t * BB + b] * ym;
            den += ym;
        }
        cb = num / den;
    }
#pragma unroll
    for (int o = 16; o > 0; o >>= 1) cb += __shfl_xor_sync(0xffffffffu, cb, o);
    if (threadIdx.x == 0) {
        out[(size_t)BB * VV]     = cb / (float)BB;
        out[(size_t)BB * VV + 1] = g_cov_sum / (float)(TY * BB);
    }
}

// ---------------- launch ----------------
extern "C" void kernel_launch(void* const* d_in, const int* in_sizes, int n_in,
                              void* d_out, int out_size) {
    const float* y_emb   = (const float*)d_in[0];
    const float* context = (const float*)d_in[1];
    const float* h0      = (const float*)d_in[2];
    const float* c0      = (const float*)d_in[3];
    const float* x_mask  = (const float*)d_in[4];
    const float* y_mask  = (const float*)d_in[5];
    const float* cov0    = (const float*)d_in[6];
    const int*   y_idx   = (const int*)d_in[7];
    const float* W_ih    = (const float*)d_in[8];
    const float* W_hh    = (const float*)d_in[9];
    const float* b_ih    = (const float*)d_in[10];
    const float* b_hh    = (const float*)d_in[11];
    const float* Wx      = (const float*)d_in[12];
    const float* Ux      = (const float*)d_in[13];
    const float* bx      = (const float*)d_in[14];
    const float* Wc_att  = (const float*)d_in[15];
    const float* b_att   = (const float*)d_in[16];
    const float* W_comb  = (const float*)d_in[17];
    const float* U_att   = (const float*)d_in[18];
    const float* W_cov   = (const float*)d_in[19];
    const float* Wp      = (const float*)d_in[20];
    const float* bp      = (const float*)d_in[21];
    float* out = (float*)d_out;

    void *p_pctx, *p_feats, *p_logits;
    cudaGetSymbolAddress(&p_pctx, g_pctx);
    cudaGetSymbolAddress(&p_feats, g_feats);
    cudaGetSymbolAddress(&p_logits, g_logits);

    init_kernel<<<1, 256>>>(h0, c0, cov0);

    // pctx = context @ Wc_att^T + b_att : M=2560, N=512, K=512
    {
        dim3 grid((TX * BB) / BMg, CC / BNg);   // (20, 4)
        gemm_abT_bias<<<grid, 256>>>(context, Wc_att, b_att, (float*)p_pctx,
                                     TX * BB, CC, CC);
    }

    decoder_kernel<<<NBLK, NTHR>>>(y_emb, context, x_mask, y_mask,
                                   W_ih, W_hh, b_ih, b_hh, Wx, Ux, bx,
                                   W_comb, U_att, W_cov);

    // logits = feats @ Wp^T + bp : M=640, N=30000, K=896
    {
        dim3 grid((TY * BB) / BMg, (VV + BNg - 1) / BNg);   // (5, 235)
        gemm_abT_bias<<<grid, 256>>>((const float*)p_feats, Wp, bp, (float*)p_logits,
                                     TY * BB, VV, FF);
    }

    softmax_cost_kernel<<<TY * BB, 256>>>(y_idx, out);
    finalize_kernel<<<1, 32>>>(y_mask, out);
}

// round 4
// speedup vs baseline: 2.7887x; 2.7338x over previous
#include <cuda_runtime.h>
#include <math.h>

#define TX 160
#define TY 40
#define BB 16
#define HH 256
#define CC 512
#define INDIM 128
#define VV 30000
#define G4 1024      // 4*H
#define FF 896       // H + C + IN

#define NBLK 128
#define NTHR 320
#define NWARPS ((NBLK * NTHR) / 32)   // 1280
#define WPB (NWARPS / BB)             // 80 warps per batch

// ---------------- device scratch (static, no allocs) ----------------
__device__ __align__(256) float g_pctx[TX * BB * CC];          // 5.24 MB
__device__ __align__(256) float g_h[BB * HH];
__device__ __align__(256) float g_c[BB * HH];
__device__ __align__(256) float g_gates[BB * G4];
__device__ __align__(256) float g_hq[BB * CC];
__device__ __align__(256) float g_acc[BB * TX];                // [b][x]
__device__ __align__(256) float g_sc[BB * TX];                 // [b][x]
__device__ __align__(256) float g_attp[5 * BB * CC];           // partial atted
__device__ __align__(256) float g_feats[TY * BB * FF];         // 2.29 MB
__device__ __align__(256) float g_logits[TY * BB * VV];        // 76.8 MB
__device__ __align__(256) float g_cost[TY * BB];
__device__ float g_cov_sum;
__device__ unsigned g_bar;

// ---------------- helpers ----------------
__device__ __forceinline__ float tanh_fast(float x) {
    float y;
    asm("tanh.approx.f32 %0, %1;" : "=f"(y) : "f"(x));
    return y;
}
__device__ __forceinline__ float sig_fast(float x) {
    return fmaf(tanh_fast(0.5f * x), 0.5f, 0.5f);
}
__device__ __forceinline__ float dot4(float4 a, float4 b) {
    return fmaf(a.x, b.x, fmaf(a.y, b.y, fmaf(a.z, b.z, a.w * b.w)));
}
__device__ __forceinline__ float warp_sum(float s) {
#pragma unroll
    for (int o = 16; o > 0; o >>= 1) s += __shfl_xor_sync(0xffffffffu, s, o);
    return s;
}

__device__ __forceinline__ unsigned long long dup2(float a) {
    unsigned long long r;
    asm("mov.b64 %0, {%1, %1};" : "=l"(r) : "f"(a));
    return r;
}
__device__ __forceinline__ void ffma2(unsigned long long& d, unsigned long long a, unsigned long long b) {
    asm("fma.rn.f32x2 %0, %1, %2, %0;" : "+l"(d) : "l"(a), "l"(b));
}
__device__ __forceinline__ void unpack2(unsigned long long v, float& lo, float& hi) {
    asm("mov.b64 {%0, %1}, %2;" : "=f"(lo), "=f"(hi) : "l"(v));
}

// monotonic grid barrier (all gridDim.x blocks co-resident)
__device__ __forceinline__ void grid_sync(unsigned& epoch) {
    __syncthreads();
    if (threadIdx.x == 0) {
        __threadfence();
        epoch += gridDim.x;
        atomicAdd(&g_bar, 1u);
        while (*((volatile unsigned*)&g_bar) < epoch) { __nanosleep(64); }
        __threadfence();
    }
    __syncthreads();
}

// ---------------- init ----------------
__global__ void init_kernel(const float* __restrict__ h0, const float* __restrict__ c0,
                            const float* __restrict__ cov0) {
    int tid = threadIdx.x;
    if (tid == 0) { g_bar = 0u; g_cov_sum = 0.f; }
    for (int i = tid; i < BB * HH; i += blockDim.x) { g_h[i] = h0[i]; g_c[i] = c0[i]; }
    // g_acc is [b][x]; cov0 is [b][x] too (init_coverage shape (B, TX))
    for (int i = tid; i < BB * TX; i += blockDim.x) { g_acc[i] = cov0[i]; }
}

// ---------------- GEMM: C = A @ B^T + bias, 128x128 tile, 8x8/thread, f32x2 ----
// Split 4+4 fragments (offsets f and f+64) for conflict-free shared loads.
#define BMg 128
#define BNg 128
#define BKg 16
#define TSTR 132   // padded stride

__global__ __launch_bounds__(256, 2) void gemm_abT_bias(
    const float* __restrict__ A, const float* __restrict__ Bm,
    const float* __restrict__ bias, float* __restrict__ Cout,
    int M, int N, int K)
{
    __shared__ __align__(16) float As[BKg * TSTR];
    __shared__ __align__(16) float Bs[BKg * TSTR];

    const int tid = threadIdx.x;
    const int tx = tid & 15;   // col groups at tx*4 and tx*4+64
    const int ty = tid >> 4;   // row groups at ty*4 and ty*4+64
    const int m0 = blockIdx.x * BMg;
    const int n0 = blockIdx.y * BNg;

    unsigned long long acc[8][4];
#pragma unroll
    for (int i = 0; i < 8; i++)
#pragma unroll
        for (int j = 0; j < 4; j++) acc[i][j] = 0ull;

    for (int k0 = 0; k0 < K; k0 += BKg) {
#pragma unroll
        for (int i = 0; i < 2; i++) {
            int f = tid + i * 256;       // 0..511
            int row = f >> 2;            // 0..127
            int kq = f & 3;              // 0..3
            float4 av = *(const float4*)(A + (size_t)(m0 + row) * K + k0 + kq * 4);
            As[(kq * 4 + 0) * TSTR + row] = av.x;
            As[(kq * 4 + 1) * TSTR + row] = av.y;
            As[(kq * 4 + 2) * TSTR + row] = av.z;
            As[(kq * 4 + 3) * TSTR + row] = av.w;
            int gn = n0 + row;
            float4 bv = make_float4(0.f, 0.f, 0.f, 0.f);
            if (gn < N) bv = *(const float4*)(Bm + (size_t)gn * K + k0 + kq * 4);
            Bs[(kq * 4 + 0) * TSTR + row] = bv.x;
            Bs[(kq * 4 + 1) * TSTR + row] = bv.y;
            Bs[(kq * 4 + 2) * TSTR + row] = bv.z;
            Bs[(kq * 4 + 3) * TSTR + row] = bv.w;
        }
        __syncthreads();
#pragma unroll
        for (int k = 0; k < BKg; k++) {
            float4 a0 = *(const float4*)&As[k * TSTR + ty * 4];
            float4 a1 = *(const float4*)&As[k * TSTR + ty * 4 + 64];
            ulonglong2 b0q = *(const ulonglong2*)&Bs[k * TSTR + tx * 4];
            ulonglong2 b1q = *(const ulonglong2*)&Bs[k * TSTR + tx * 4 + 64];
            unsigned long long b0 = b0q.x, b1 = b0q.y, b2 = b1q.x, b3 = b1q.y;
            float af[8] = {a0.x, a0.y, a0.z, a0.w, a1.x, a1.y, a1.z, a1.w};
#pragma unroll
            for (int i = 0; i < 8; i++) {
                unsigned long long a2 = dup2(af[i]);
                ffma2(acc[i][0], a2, b0);
                ffma2(acc[i][1], a2, b1);
                ffma2(acc[i][2], a2, b2);
                ffma2(acc[i][3], a2, b3);
            }
        }
        __syncthreads();
    }
#pragma unroll
    for (int i = 0; i < 8; i++) {
        int m = m0 + ((i < 4) ? (ty * 4 + i) : (64 + ty * 4 + i - 4));
#pragma unroll
        for (int j = 0; j < 4; j++) {
            int n = n0 + ((j < 2) ? (tx * 4 + j * 2) : (64 + tx * 4 + (j - 2) * 2));
            float lo, hi;
            unpack2(acc[i][j], lo, hi);
            if (n < N)     Cout[(size_t)m * N + n]     = lo + bias[n];
            if (n + 1 < N) Cout[(size_t)m * N + n + 1] = hi + bias[n + 1];
        }
    }
}

// ---------------- persistent recurrence (warp-cooperative) ----------------
__global__ __launch_bounds__(NTHR) void decoder_kernel(
    const float* __restrict__ y_emb, const float* __restrict__ context,
    const float* __restrict__ x_mask, const float* __restrict__ y_mask,
    const float* __restrict__ W_ih, const float* __restrict__ W_hh,
    const float* __restrict__ b_ih, const float* __restrict__ b_hh,
    const float* __restrict__ Wx, const float* __restrict__ Ux, const float* __restrict__ bx,
    const float* __restrict__ W_comb, const float* __restrict__ U_att,
    const float* __restrict__ W_cov)
{
    __shared__ __align__(16) float sh_h1[BB * HH];
    __shared__ __align__(16) float sh_c1[BB * HH];
    __shared__ __align__(16) float sh_watt[BB * TX];   // [b][x]
    __shared__ __align__(16) float sh_wcov[CC];
    __shared__ __align__(16) float sh_uatt[CC];

    const int tid = threadIdx.x;
    const int gtid = blockIdx.x * NTHR + tid;
    const int lane = tid & 31;
    const int lwid = tid >> 5;          // 0..9
    const int gwid = gtid >> 5;         // 0..1279
    const int wb = gwid / WPB;          // batch this warp serves (0..15)
    const int wslot = gwid % WPB;       // 0..79
    unsigned epoch = 0;

    for (int i = tid; i < CC; i += NTHR) { sh_wcov[i] = W_cov[i]; sh_uatt[i] = U_att[i]; }
    __syncthreads();

    for (int t = 0; t < TY; t++) {
        const float* yrow = y_emb + (size_t)t * BB * INDIM;

        // ---- P1: gates[b][j] = y_t[b]·W_ih[j] + h[b]·W_hh[j] + b_ih[j]+b_hh[j]
        {
            float4 y4  = *(const float4*)(yrow + wb * INDIM + lane * 4);
            float4 h4a = *(const float4*)(g_h + wb * HH + lane * 4);
            float4 h4b = *(const float4*)(g_h + wb * HH + 128 + lane * 4);
            for (int j = wslot; j < G4; j += WPB) {
                float4 w0 = *(const float4*)(W_ih + (size_t)j * INDIM + lane * 4);
                float4 w1 = *(const float4*)(W_hh + (size_t)j * HH + lane * 4);
                float4 w2 = *(const float4*)(W_hh + (size_t)j * HH + 128 + lane * 4);
                float s = dot4(w0, y4) + dot4(w1, h4a) + dot4(w2, h4b);
                s = warp_sum(s);
                if (lane == 0) g_gates[wb * G4 + j] = s + b_ih[j] + b_hh[j];
            }
        }
        grid_sync(epoch);

        // ---- P2: LSTM cell 1, redundant per block into smem
        for (int idx = tid; idx < BB * HH; idx += NTHR) {
            int b = idx >> 8, u = idx & 255;
            const float* gb = g_gates + b * G4 + u;
            float gi = gb[0], gf = gb[HH], gg = gb[2 * HH], go = gb[3 * HH];
            float c_old = g_c[idx], h_old = g_h[idx];
            float c1 = sig_fast(gf) * c_old + sig_fast(gi) * tanh_fast(gg);
            float h1 = sig_fast(go) * tanh_fast(c1);
            float ym = y_mask[t * BB + b];
            sh_h1[idx] = ym * h1 + (1.f - ym) * h_old;
            sh_c1[idx] = ym * c1 + (1.f - ym) * c_old;
        }
        __syncthreads();

        // ---- P3: hq[b][o] = [h1;c1][b] · W_comb[o]
        {
            float4 xa = *(const float4*)(sh_h1 + wb * HH + lane * 4);
            float4 xb = *(const float4*)(sh_h1 + wb * HH + 128 + lane * 4);
            float4 xc = *(const float4*)(sh_c1 + wb * HH + lane * 4);
            float4 xd = *(const float4*)(sh_c1 + wb * HH + 128 + lane * 4);
            for (int o = wslot; o < CC; o += WPB) {
                const float* wr = W_comb + (size_t)o * (2 * HH);
                float4 w0 = *(const float4*)(wr + lane * 4);
                float4 w1 = *(const float4*)(wr + 128 + lane * 4);
                float4 w2 = *(const float4*)(wr + 256 + lane * 4);
                float4 w3 = *(const float4*)(wr + 384 + lane * 4);
                float s = dot4(w0, xa) + dot4(w1, xb) + dot4(w2, xc) + dot4(w3, xd);
                s = warp_sum(s);
                if (lane == 0) g_hq[wb * CC + o] = s;
            }
        }
        grid_sync(epoch);

        // ---- P4: attention scores, warp per (x,b), exactly 2 rounds
        for (int p = gwid; p < TX * BB; p += NWARPS) {
            int x = p >> 4, b = p & 15;
            float accv = g_acc[b * TX + x];
            const float* pc = g_pctx + (size_t)p * CC;
            const float* hqb = g_hq + b * CC;
            float s = 0.f;
#pragma unroll
            for (int i = 0; i < CC / 32; i++) {
                int c = lane + 32 * i;
                s += tanh_fast(fmaf(accv, sh_wcov[c], pc[c] + hqb[c])) * sh_uatt[c];
            }
            s = warp_sum(s);
            if (lane == 0) g_sc[b * TX + x] = x_mask[p] * s;
        }
        grid_sync(epoch);

        // ---- P5a: softmax weights, redundant per block into smem [b][x]
        for (int b = lwid; b < BB; b += NTHR / 32) {
            const float* scb = g_sc + b * TX;
            float mx = -3.4e38f;
#pragma unroll
            for (int i = 0; i < TX / 32; i++) mx = fmaxf(mx, scb[lane + 32 * i]);
#pragma unroll
            for (int o = 16; o > 0; o >>= 1) mx = fmaxf(mx, __shfl_xor_sync(0xffffffffu, mx, o));
            float e[TX / 32]; float sm = 0.f;
#pragma unroll
            for (int i = 0; i < TX / 32; i++) {
                int x = lane + 32 * i;
                e[i] = __expf(scb[x] - mx) * x_mask[x * BB + b];
                sm += e[i];
            }
            sm = warp_sum(sm);
            float inv = __fdividef(1.f, sm);
#pragma unroll
            for (int i = 0; i < TX / 32; i++) sh_watt[b * TX + lane + 32 * i] = e[i] * inv;
        }
        __syncthreads();

        // ---- P5b: partial atted over x-chunks; 1280 jobs == 1280 warps
        {
            int xck = gwid % 5;
            int rest = gwid / 5;            // 0..255
            int b = rest >> 4, cck = rest & 15;
            int c = cck * 32 + lane;
            float s = 0.f;
#pragma unroll 8
            for (int i = 0; i < 32; i++) {
                int x = xck * 32 + i;
                s = fmaf(sh_watt[b * TX + x], context[(size_t)(x * BB + b) * CC + c], s);
            }
            g_attp[xck * (BB * CC) + b * CC + c] = s;
        }
        // coverage update on block 0 ([b][x] layouts match)
        if (blockIdx.x == 0) {
            float part = 0.f;
            for (int i = tid; i < BB * TX; i += NTHR) {
                float w = sh_watt[i];
                float old = g_acc[i];
                part += fminf(w, old);
                g_acc[i] = old + w;
            }
            part = warp_sum(part);
            if (lane == 0) atomicAdd(&g_cov_sum, part);
        }
        grid_sync(epoch);

        // ---- P6+P7 fused: warp owns (b,u) with all 4 gates, then cell 2
        {
            float4 xh1a = *(const float4*)(sh_h1 + wb * HH + lane * 4);
            float4 xh1b = *(const float4*)(sh_h1 + wb * HH + 128 + lane * 4);
            float4 at4[4];
#pragma unroll
            for (int m = 0; m < 4; m++) {
                float4 s = make_float4(0.f, 0.f, 0.f, 0.f);
#pragma unroll
                for (int k = 0; k < 5; k++) {
                    float4 v = *(const float4*)(g_attp + k * (BB * CC) + wb * CC + m * 128 + lane * 4);
                    s.x += v.x; s.y += v.y; s.z += v.z; s.w += v.w;
                }
                at4[m] = s;
            }
            float ym = y_mask[t * BB + wb];
            for (int u = wslot; u < HH; u += WPB) {
                float sg[4];
#pragma unroll
                for (int g = 0; g < 4; g++) {
                    int j = u + g * HH;
                    float4 u0 = *(const float4*)(Ux + (size_t)j * HH + lane * 4);
                    float4 u1 = *(const float4*)(Ux + (size_t)j * HH + 128 + lane * 4);
                    float s = dot4(u0, xh1a) + dot4(u1, xh1b);
                    const float* wxr = Wx + (size_t)j * CC;
#pragma unroll
                    for (int m = 0; m < 4; m++) {
                        float4 wv = *(const float4*)(wxr + m * 128 + lane * 4);
                        s += dot4(wv, at4[m]);
                    }
                    sg[g] = warp_sum(s);
                }
                if (lane == 0) {
                    float i2 = sg[0] + bx[u],          f2 = sg[1] + bx[u + HH];
                    float o2 = sg[2] + bx[u + 2 * HH], g2 = sg[3] + bx[u + 3 * HH];
                    int idx = wb * HH + u;
                    float c1 = sh_c1[idx], h1 = sh_h1[idx];
                    float c2 = sig_fast(f2) * c1 + sig_fast(i2) * tanh_fast(g2);
                    float h2 = sig_fast(o2) * tanh_fast(c2);
                    c2 = ym * c2 + (1.f - ym) * c1;
                    h2 = ym * h2 + (1.f - ym) * h1;
                    g_h[idx] = h2; g_c[idx] = c2;
                    g_feats[(size_t)(t * BB + wb) * FF + u] = h2;
                }
            }
        }
        // feats tail: atted sum-of-partials + y copy
        for (int idx = gtid; idx < BB * (CC + INDIM); idx += NBLK * NTHR) {
            if (idx < BB * CC) {
                int b = idx >> 9, c = idx & 511;
                float s = 0.f;
#pragma unroll
                for (int k = 0; k < 5; k++) s += g_attp[k * (BB * CC) + idx];
                g_feats[(size_t)(t * BB + b) * FF + HH + c] = s;
            } else {
                int q = idx - BB * CC;
                int b = q >> 7, kk = q & 127;
                g_feats[(size_t)(t * BB + b) * FF + HH + CC + kk] = yrow[b * INDIM + kk];
            }
        }
        grid_sync(epoch);
    }
}

// ---------------- softmax / cost per row ----------------
__global__ __launch_bounds__(256) void softmax_cost_kernel(const int* __restrict__ y_idx,
                                                           float* __restrict__ out) {
    __shared__ float sred[256];
    __shared__ float s_mx, s_sum;
    const int m = blockIdx.x;
    const int tid = threadIdx.x;
    const float* row = g_logits + (size_t)m * VV;

    float mx = -3.4e38f;
    for (int v = tid; v < VV; v += 256) mx = fmaxf(mx, row[v]);
    sred[tid] = mx; __syncthreads();
    for (int s = 128; s > 0; s >>= 1) {
        if (tid < s) sred[tid] = fmaxf(sred[tid], sred[tid + s]);
        __syncthreads();
    }
    if (tid == 0) s_mx = sred[0];
    __syncthreads();
    mx = s_mx;

    float sm = 0.f;
    for (int v = tid; v < VV; v += 256) sm += __expf(row[v] - mx);
    sred[tid] = sm; __syncthreads();
    for (int s = 128; s > 0; s >>= 1) {
        if (tid < s) sred[tid] += sred[tid + s];
        __syncthreads();
    }
    if (tid == 0) {
        s_sum = sred[0];
        float lz = mx + logf(sred[0]);
        g_cost[m] = lz - row[y_idx[m]];
    }
    __syncthreads();

    if (m >= (TY - 1) * BB) {
        int b = m - (TY - 1) * BB;
        float inv = __fdividef(1.f, s_sum);
        for (int v = tid; v < VV; v += 256)
            out[(size_t)b * VV + v] = __expf(row[v] - mx) * inv;
    }
}

// ---------------- final scalars ----------------
__global__ void finalize_kernel(const float* __restrict__ y_mask, float* __restrict__ out) {
    int b = threadIdx.x;
    float cb = 0.f;
    if (b < BB) {
        float num = 0.f, den = 0.f;
        for (int t = 0; t < TY; t++) {
            float ym = y_mask[t * BB + b];
            num += g_cost[t * BB + b] * ym;
            den += ym;
        }
        cb = num / den;
    }
#pragma unroll
    for (int o = 16; o > 0; o >>= 1) cb += __shfl_xor_sync(0xffffffffu, cb, o);
    if (threadIdx.x == 0) {
        out[(size_t)BB * VV]     = cb / (float)BB;
        out[(size_t)BB * VV + 1] = g_cov_sum / (float)(TY * BB);
    }
}

// ---------------- launch ----------------
extern "C" void kernel_launch(void* const* d_in, const int* in_sizes, int n_in,
                              void* d_out, int out_size) {
    const float* y_emb   = (const float*)d_in[0];
    const float* context = (const float*)d_in[1];
    const float* h0      = (const float*)d_in[2];
    const float* c0      = (const float*)d_in[3];
    const float* x_mask  = (const float*)d_in[4];
    const float* y_mask  = (const float*)d_in[5];
    const float* cov0    = (const float*)d_in[6];
    const int*   y_idx   = (const int*)d_in[7];
    const float* W_ih    = (const float*)d_in[8];
    const float* W_hh    = (const float*)d_in[9];
    const float* b_ih    = (const float*)d_in[10];
    const float* b_hh    = (const float*)d_in[11];
    const float* Wx      = (const float*)d_in[12];
    const float* Ux      = (const float*)d_in[13];
    const float* bx      = (const float*)d_in[14];
    const float* Wc_att  = (const float*)d_in[15];
    const float* b_att   = (const float*)d_in[16];
    const float* W_comb  = (const float*)d_in[17];
    const float* U_att   = (const float*)d_in[18];
    const float* W_cov   = (const float*)d_in[19];
    const float* Wp      = (const float*)d_in[20];
    const float* bp      = (const float*)d_in[21];
    float* out = (float*)d_out;

    void *p_pctx, *p_feats, *p_logits;
    cudaGetSymbolAddress(&p_pctx, g_pctx);
    cudaGetSymbolAddress(&p_feats, g_feats);
    cudaGetSymbolAddress(&p_logits, g_logits);

    init_kernel<<<1, 256>>>(h0, c0, cov0);

    // pctx = context @ Wc_att^T + b_att : M=2560, N=512, K=512
    {
        dim3 grid((TX * BB) / BMg, CC / BNg);   // (20, 4)
        gemm_abT_bias<<<grid, 256>>>(context, Wc_att, b_att, (float*)p_pctx,
                                     TX * BB, CC, CC);
    }

    decoder_kernel<<<NBLK, NTHR>>>(y_emb, context, x_mask, y_mask,
                                   W_ih, W_hh, b_ih, b_hh, Wx, Ux, bx,
                                   W_comb, U_att, W_cov);

    // logits = feats @ Wp^T + bp : M=640, N=30000, K=896
    {
        dim3 grid((TY * BB) / BMg, (VV + BNg - 1) / BNg);   // (5, 235)
        gemm_abT_bias<<<grid, 256>>>((const float*)p_feats, Wp, bp, (float*)p_logits,
                                     TY * BB, VV, FF);
    }

    softmax_cost_kernel<<<TY * BB, 256>>>(y_idx, out);
    finalize_kernel<<<1, 32>>>(y_mask, out);
}

// round 6
// speedup vs baseline: 2.8584x; 1.0250x over previous
#include <cuda_runtime.h>
#include <math.h>

#define TX 160
#define TY 40
#define BB 16
#define HH 256
#define CC 512
#define INDIM 128
#define VV 30000
#define G4 1024      // 4*H
#define FF 896       // H + C + IN

#define NBLK 128
#define NTHR 320
#define NWARPS ((NBLK * NTHR) / 32)   // 1280
#define WPB (NWARPS / BB)             // 80 warps per batch

// ---------------- device scratch (static, no allocs) ----------------
__device__ __align__(256) float g_pctx[TX * BB * CC];          // 5.24 MB
__device__ __align__(256) float g_h[BB * HH];
__device__ __align__(256) float g_c[BB * HH];
__device__ __align__(256) float g_gates[BB * G4];
__device__ __align__(256) float g_hq[BB * CC];
__device__ __align__(256) float g_acc[BB * TX];                // [b][x]
__device__ __align__(256) float g_sc[BB * TX];                 // [b][x]
__device__ __align__(256) float g_attp[5 * BB * CC];           // partial atted
__device__ __align__(256) float g_feats[TY * BB * FF];         // 2.29 MB
__device__ __align__(256) float g_logits[TY * BB * VV];        // 76.8 MB
__device__ __align__(256) float g_cost[TY * BB];
__device__ float g_cov_sum;
__device__ __align__(128) unsigned g_bar;

// ---------------- helpers ----------------
__device__ __forceinline__ float tanh_fast(float x) {
    float y;
    asm("tanh.approx.f32 %0, %1;" : "=f"(y) : "f"(x));
    return y;
}
__device__ __forceinline__ float sig_fast(float x) {
    return fmaf(tanh_fast(0.5f * x), 0.5f, 0.5f);
}
__device__ __forceinline__ float dot4(float4 a, float4 b) {
    return fmaf(a.x, b.x, fmaf(a.y, b.y, fmaf(a.z, b.z, a.w * b.w)));
}
__device__ __forceinline__ float warp_sum(float s) {
#pragma unroll
    for (int o = 16; o > 0; o >>= 1) s += __shfl_xor_sync(0xffffffffu, s, o);
    return s;
}

__device__ __forceinline__ unsigned long long dup2(float a) {
    unsigned long long r;
    asm("mov.b64 %0, {%1, %1};" : "=l"(r) : "f"(a));
    return r;
}
__device__ __forceinline__ void ffma2(unsigned long long& d, unsigned long long a, unsigned long long b) {
    asm("fma.rn.f32x2 %0, %1, %2, %0;" : "+l"(d) : "l"(a), "l"(b));
}
__device__ __forceinline__ void unpack2(unsigned long long v, float& lo, float& hi) {
    asm("mov.b64 {%0, %1}, %2;" : "=f"(lo), "=f"(hi) : "l"(v));
}

// fast monotonic grid barrier: no-return red arrival + polite acquire poll
__device__ __forceinline__ void grid_sync(unsigned& epoch) {
    __syncthreads();
    if (threadIdx.x == 0) {
        epoch += gridDim.x;
        asm volatile("red.release.gpu.global.add.u32 [%0], 1;" :: "l"(&g_bar) : "memory");
        unsigned v;
        while (true) {
            asm volatile("ld.acquire.gpu.global.u32 %0, [%1];" : "=r"(v) : "l"(&g_bar) : "memory");
            if (v >= epoch) break;
            __nanosleep(32);
        }
    }
    __syncthreads();
}

// ---------------- init ----------------
__global__ void init_kernel(const float* __restrict__ h0, const float* __restrict__ c0,
                            const float* __restrict__ cov0) {
    int tid = threadIdx.x;
    if (tid == 0) { g_bar = 0u; g_cov_sum = 0.f; }
    for (int i = tid; i < BB * HH; i += blockDim.x) { g_h[i] = h0[i]; g_c[i] = c0[i]; }
    for (int i = tid; i < BB * TX; i += blockDim.x) { g_acc[i] = cov0[i]; }
}

// ---------------- GEMM: C = A @ B^T + bias, 128x128 tile, 8x8/thread, f32x2 ----
// Register-staged pipeline: prefetch next K-tile's LDGs before the FFMA loop.
#define BMg 128
#define BNg 128
#define BKg 16
#define TSTR 132   // padded stride

__global__ __launch_bounds__(256, 2) void gemm_abT_bias(
    const float* __restrict__ A, const float* __restrict__ Bm,
    const float* __restrict__ bias, float* __restrict__ Cout,
    int M, int N, int K)
{
    __shared__ __align__(16) float As[BKg * TSTR];
    __shared__ __align__(16) float Bs[BKg * TSTR];

    const int tid = threadIdx.x;
    const int tx = tid & 15;
    const int ty = tid >> 4;
    const int m0 = blockIdx.x * BMg;
    const int n0 = blockIdx.y * BNg;

    unsigned long long acc[8][4];
#pragma unroll
    for (int i = 0; i < 8; i++)
#pragma unroll
        for (int j = 0; j < 4; j++) acc[i][j] = 0ull;

    float4 sa[2], sb[2];
    // prologue: load tile 0 into registers
#pragma unroll
    for (int i = 0; i < 2; i++) {
        int f = tid + i * 256;
        int row = f >> 2, kq = f & 3;
        sa[i] = *(const float4*)(A + (size_t)(m0 + row) * K + kq * 4);
        int gn = n0 + row;
        sb[i] = make_float4(0.f, 0.f, 0.f, 0.f);
        if (gn < N) sb[i] = *(const float4*)(Bm + (size_t)gn * K + kq * 4);
    }

    for (int k0 = 0; k0 < K; k0 += BKg) {
        // store staged tile into smem (transposed)
#pragma unroll
        for (int i = 0; i < 2; i++) {
            int f = tid + i * 256;
            int row = f >> 2, kq = f & 3;
            As[(kq * 4 + 0) * TSTR + row] = sa[i].x;
            As[(kq * 4 + 1) * TSTR + row] = sa[i].y;
            As[(kq * 4 + 2) * TSTR + row] = sa[i].z;
            As[(kq * 4 + 3) * TSTR + row] = sa[i].w;
            Bs[(kq * 4 + 0) * TSTR + row] = sb[i].x;
            Bs[(kq * 4 + 1) * TSTR + row] = sb[i].y;
            Bs[(kq * 4 + 2) * TSTR + row] = sb[i].z;
            Bs[(kq * 4 + 3) * TSTR + row] = sb[i].w;
        }
        __syncthreads();
        // prefetch next tile (overlaps with compute below)
        if (k0 + BKg < K) {
#pragma unroll
            for (int i = 0; i < 2; i++) {
                int f = tid + i * 256;
                int row = f >> 2, kq = f & 3;
                sa[i] = *(const float4*)(A + (size_t)(m0 + row) * K + (k0 + BKg) + kq * 4);
                int gn = n0 + row;
                sb[i] = make_float4(0.f, 0.f, 0.f, 0.f);
                if (gn < N) sb[i] = *(const float4*)(Bm + (size_t)gn * K + (k0 + BKg) + kq * 4);
            }
        }
#pragma unroll
        for (int k = 0; k < BKg; k++) {
            float4 a0 = *(const float4*)&As[k * TSTR + ty * 4];
            float4 a1 = *(const float4*)&As[k * TSTR + ty * 4 + 64];
            ulonglong2 b0q = *(const ulonglong2*)&Bs[k * TSTR + tx * 4];
            ulonglong2 b1q = *(const ulonglong2*)&Bs[k * TSTR + tx * 4 + 64];
            unsigned long long b0 = b0q.x, b1 = b0q.y, b2 = b1q.x, b3 = b1q.y;
            float af[8] = {a0.x, a0.y, a0.z, a0.w, a1.x, a1.y, a1.z, a1.w};
#pragma unroll
            for (int i = 0; i < 8; i++) {
                unsigned long long a2 = dup2(af[i]);
                ffma2(acc[i][0], a2, b0);
                ffma2(acc[i][1], a2, b1);
                ffma2(acc[i][2], a2, b2);
                ffma2(acc[i][3], a2, b3);
            }
        }
        __syncthreads();
    }
#pragma unroll
    for (int i = 0; i < 8; i++) {
        int m = m0 + ((i < 4) ? (ty * 4 + i) : (64 + ty * 4 + i - 4));
#pragma unroll
        for (int j = 0; j < 4; j++) {
            int n = n0 + ((j < 2) ? (tx * 4 + j * 2) : (64 + tx * 4 + (j - 2) * 2));
            float lo, hi;
            unpack2(acc[i][j], lo, hi);
            if (n < N)     Cout[(size_t)m * N + n]     = lo + bias[n];
            if (n + 1 < N) Cout[(size_t)m * N + n + 1] = hi + bias[n + 1];
        }
    }
}

// ---------------- persistent recurrence (warp-cooperative) ----------------
__global__ __launch_bounds__(NTHR) void decoder_kernel(
    const float* __restrict__ y_emb, const float* __restrict__ context,
    const float* __restrict__ x_mask, const float* __restrict__ y_mask,
    const float* __restrict__ W_ih, const float* __restrict__ W_hh,
    const float* __restrict__ b_ih, const float* __restrict__ b_hh,
    const float* __restrict__ Wx, const float* __restrict__ Ux, const float* __restrict__ bx,
    const float* __restrict__ W_comb, const float* __restrict__ U_att,
    const float* __restrict__ W_cov)
{
    __shared__ __align__(16) float sh_h1[BB * HH];
    __shared__ __align__(16) float sh_c1[BB * HH];
    __shared__ __align__(16) float sh_watt[BB * TX];   // [b][x]
    __shared__ __align__(16) float sh_wcov[CC];
    __shared__ __align__(16) float sh_uatt[CC];

    const int tid = threadIdx.x;
    const int gtid = blockIdx.x * NTHR + tid;
    const int lane = tid & 31;
    const int lwid = tid >> 5;          // 0..9
    const int gwid = gtid >> 5;         // 0..1279
    const int wb = gwid / WPB;          // batch this warp serves (0..15)
    const int wslot = gwid % WPB;       // 0..79
    unsigned epoch = 0;

    for (int i = tid; i < CC; i += NTHR) { sh_wcov[i] = W_cov[i]; sh_uatt[i] = U_att[i]; }
    __syncthreads();

    for (int t = 0; t < TY; t++) {
        const float* yrow = y_emb + (size_t)t * BB * INDIM;

        // ---- P1: gates[b][j] = y_t[b]·W_ih[j] + h[b]·W_hh[j] + b_ih[j]+b_hh[j]
        {
            float4 y4  = *(const float4*)(yrow + wb * INDIM + lane * 4);
            float4 h4a = *(const float4*)(g_h + wb * HH + lane * 4);
            float4 h4b = *(const float4*)(g_h + wb * HH + 128 + lane * 4);
            for (int j = wslot; j < G4; j += WPB) {
                float4 w0 = *(const float4*)(W_ih + (size_t)j * INDIM + lane * 4);
                float4 w1 = *(const float4*)(W_hh + (size_t)j * HH + lane * 4);
                float4 w2 = *(const float4*)(W_hh + (size_t)j * HH + 128 + lane * 4);
                float s = dot4(w0, y4) + dot4(w1, h4a) + dot4(w2, h4b);
                s = warp_sum(s);
                if (lane == 0) g_gates[wb * G4 + j] = s + b_ih[j] + b_hh[j];
            }
        }
        grid_sync(epoch);

        // ---- P2: LSTM cell 1, redundant per block into smem
        for (int idx = tid; idx < BB * HH; idx += NTHR) {
            int b = idx >> 8, u = idx & 255;
            const float* gb = g_gates + b * G4 + u;
            float gi = gb[0], gf = gb[HH], gg = gb[2 * HH], go = gb[3 * HH];
            float c_old = g_c[idx], h_old = g_h[idx];
            float c1 = sig_fast(gf) * c_old + sig_fast(gi) * tanh_fast(gg);
            float h1 = sig_fast(go) * tanh_fast(c1);
            float ym = y_mask[t * BB + b];
            sh_h1[idx] = ym * h1 + (1.f - ym) * h_old;
            sh_c1[idx] = ym * c1 + (1.f - ym) * c_old;
        }
        __syncthreads();

        // ---- P3: hq[b][o] = [h1;c1][b] · W_comb[o]
        {
            float4 xa = *(const float4*)(sh_h1 + wb * HH + lane * 4);
            float4 xb = *(const float4*)(sh_h1 + wb * HH + 128 + lane * 4);
            float4 xc = *(const float4*)(sh_c1 + wb * HH + lane * 4);
            float4 xd = *(const float4*)(sh_c1 + wb * HH + 128 + lane * 4);
            for (int o = wslot; o < CC; o += WPB) {
                const float* wr = W_comb + (size_t)o * (2 * HH);
                float4 w0 = *(const float4*)(wr + lane * 4);
                float4 w1 = *(const float4*)(wr + 128 + lane * 4);
                float4 w2 = *(const float4*)(wr + 256 + lane * 4);
                float4 w3 = *(const float4*)(wr + 384 + lane * 4);
                float s = dot4(w0, xa) + dot4(w1, xb) + dot4(w2, xc) + dot4(w3, xd);
                s = warp_sum(s);
                if (lane == 0) g_hq[wb * CC + o] = s;
            }
        }
        grid_sync(epoch);

        // ---- P4: attention scores, warp per (x,b), exactly 2 rounds
        for (int p = gwid; p < TX * BB; p += NWARPS) {
            int x = p >> 4, b = p & 15;
            float accv = g_acc[b * TX + x];
            const float* pc = g_pctx + (size_t)p * CC;
            const float* hqb = g_hq + b * CC;
            float s = 0.f;
#pragma unroll
            for (int i = 0; i < CC / 32; i++) {
                int c = lane + 32 * i;
                s += tanh_fast(fmaf(accv, sh_wcov[c], pc[c] + hqb[c])) * sh_uatt[c];
            }
            s = warp_sum(s);
            if (lane == 0) g_sc[b * TX + x] = x_mask[p] * s;
        }
        grid_sync(epoch);

        // ---- P5a: softmax weights, redundant per block into smem [b][x]
        for (int b = lwid; b < BB; b += NTHR / 32) {
            const float* scb = g_sc + b * TX;
            float mx = -3.4e38f;
#pragma unroll
            for (int i = 0; i < TX / 32; i++) mx = fmaxf(mx, scb[lane + 32 * i]);
#pragma unroll
            for (int o = 16; o > 0; o >>= 1) mx = fmaxf(mx, __shfl_xor_sync(0xffffffffu, mx, o));
            float e[TX / 32]; float sm = 0.f;
#pragma unroll
            for (int i = 0; i < TX / 32; i++) {
                int x = lane + 32 * i;
                e[i] = __expf(scb[x] - mx) * x_mask[x * BB + b];
                sm += e[i];
            }
            sm = warp_sum(sm);
            float inv = __fdividef(1.f, sm);
#pragma unroll
            for (int i = 0; i < TX / 32; i++) sh_watt[b * TX + lane + 32 * i] = e[i] * inv;
        }
        __syncthreads();

        // ---- P5b: partial atted over x-chunks; 1280 jobs == 1280 warps
        {
            int xck = gwid % 5;
            int rest = gwid / 5;            // 0..255
            int b = rest >> 4, cck = rest & 15;
            int c = cck * 32 + lane;
            float s = 0.f;
#pragma unroll 8
            for (int i = 0; i < 32; i++) {
                int x = xck * 32 + i;
                s = fmaf(sh_watt[b * TX + x], context[(size_t)(x * BB + b) * CC + c], s);
            }
            g_attp[xck * (BB * CC) + b * CC + c] = s;
        }
        // coverage update on block 0 ([b][x] layouts match)
        if (blockIdx.x == 0) {
            float part = 0.f;
            for (int i = tid; i < BB * TX; i += NTHR) {
                float w = sh_watt[i];
                float old = g_acc[i];
                part += fminf(w, old);
                g_acc[i] = old + w;
            }
            part = warp_sum(part);
            if (lane == 0) atomicAdd(&g_cov_sum, part);
        }
        grid_sync(epoch);

        // ---- P6+P7 fused: warp owns (b,u) with all 4 gates, then cell 2
        {
            float4 xh1a = *(const float4*)(sh_h1 + wb * HH + lane * 4);
            float4 xh1b = *(const float4*)(sh_h1 + wb * HH + 128 + lane * 4);
            float4 at4[4];
#pragma unroll
            for (int m = 0; m < 4; m++) {
                float4 s = make_float4(0.f, 0.f, 0.f, 0.f);
#pragma unroll
                for (int k = 0; k < 5; k++) {
                    float4 v = *(const float4*)(g_attp + k * (BB * CC) + wb * CC + m * 128 + lane * 4);
                    s.x += v.x; s.y += v.y; s.z += v.z; s.w += v.w;
                }
                at4[m] = s;
            }
            float ym = y_mask[t * BB + wb];
            for (int u = wslot; u < HH; u += WPB) {
                float sg[4];
#pragma unroll
                for (int g = 0; g < 4; g++) {
                    int j = u + g * HH;
                    float4 u0 = *(const float4*)(Ux + (size_t)j * HH + lane * 4);
                    float4 u1 = *(const float4*)(Ux + (size_t)j * HH + 128 + lane * 4);
                    float s = dot4(u0, xh1a) + dot4(u1, xh1b);
                    const float* wxr = Wx + (size_t)j * CC;
#pragma unroll
                    for (int m = 0; m < 4; m++) {
                        float4 wv = *(const float4*)(wxr + m * 128 + lane * 4);
                        s += dot4(wv, at4[m]);
                    }
                    sg[g] = warp_sum(s);
                }
                if (lane == 0) {
                    float i2 = sg[0] + bx[u],          f2 = sg[1] + bx[u + HH];
                    float o2 = sg[2] + bx[u + 2 * HH], g2 = sg[3] + bx[u + 3 * HH];
                    int idx = wb * HH + u;
                    float c1 = sh_c1[idx], h1 = sh_h1[idx];
                    float c2 = sig_fast(f2) * c1 + sig_fast(i2) * tanh_fast(g2);
                    float h2 = sig_fast(o2) * tanh_fast(c2);
                    c2 = ym * c2 + (1.f - ym) * c1;
                    h2 = ym * h2 + (1.f - ym) * h1;
                    g_h[idx] = h2; g_c[idx] = c2;
                    g_feats[(size_t)(t * BB + wb) * FF + u] = h2;
                }
            }
        }
        // feats tail: atted sum-of-partials + y copy
        for (int idx = gtid; idx < BB * (CC + INDIM); idx += NBLK * NTHR) {
            if (idx < BB * CC) {
                int b = idx >> 9, c = idx & 511;
                float s = 0.f;
#pragma unroll
                for (int k = 0; k < 5; k++) s += g_attp[k * (BB * CC) + idx];
                g_feats[(size_t)(t * BB + b) * FF + HH + c] = s;
            } else {
                int q = idx - BB * CC;
                int b = q >> 7, kk = q & 127;
                g_feats[(size_t)(t * BB + b) * FF + HH + CC + kk] = yrow[b * INDIM + kk];
            }
        }
        grid_sync(epoch);
    }
}

// ---------------- online softmax / cost per row (single pass) ----------------
__global__ __launch_bounds__(256) void softmax_cost_kernel(const int* __restrict__ y_idx,
                                                           float* __restrict__ out) {
    __shared__ float smx[256], ssm[256];
    const int m = blockIdx.x;
    const int tid = threadIdx.x;
    const float* row = g_logits + (size_t)m * VV;

    float mx = -3.4e38f, sm = 0.f;
    for (int v = tid; v < VV; v += 256) {
        float x = row[v];
        float nm = fmaxf(mx, x);
        sm = sm * __expf(mx - nm) + __expf(x - nm);
        mx = nm;
    }
    smx[tid] = mx; ssm[tid] = sm; __syncthreads();
    for (int s = 128; s > 0; s >>= 1) {
        if (tid < s) {
            float m2 = smx[tid + s], s2 = ssm[tid + s];
            float nm = fmaxf(smx[tid], m2);
            ssm[tid] = ssm[tid] * __expf(smx[tid] - nm) + s2 * __expf(m2 - nm);
            smx[tid] = nm;
        }
        __syncthreads();
    }
    float M = smx[0], S = ssm[0];
    if (tid == 0) g_cost[m] = M + logf(S) - row[y_idx[m]];

    if (m >= (TY - 1) * BB) {
        int b = m - (TY - 1) * BB;
        float inv = __fdividef(1.f, S);
        for (int v = tid; v < VV; v += 256)
            out[(size_t)b * VV + v] = __expf(row[v] - M) * inv;
    }
}

// ---------------- final scalars ----------------
__global__ void finalize_kernel(const float* __restrict__ y_mask, float* __restrict__ out) {
    int b = threadIdx.x;
    float cb = 0.f;
    if (b < BB) {
        float num = 0.f, den = 0.f;
        for (int t = 0; t < TY; t++) {
            float ym = y_mask[t * BB + b];
            num += g_cost[t * BB + b] * ym;
            den += ym;
        }
        cb = num / den;
    }
#pragma unroll
    for (int o = 16; o > 0; o >>= 1) cb += __shfl_xor_sync(0xffffffffu, cb, o);
    if (threadIdx.x == 0) {
        out[(size_t)BB * VV]     = cb / (float)BB;
        out[(size_t)BB * VV + 1] = g_cov_sum / (float)(TY * BB);
    }
}

// ---------------- launch ----------------
extern "C" void kernel_launch(void* const* d_in, const int* in_sizes, int n_in,
                              void* d_out, int out_size) {
    const float* y_emb   = (const float*)d_in[0];
    const float* context = (const float*)d_in[1];
    const float* h0      = (const float*)d_in[2];
    const float* c0      = (const float*)d_in[3];
    const float* x_mask  = (const float*)d_in[4];
    const float* y_mask  = (const float*)d_in[5];
    const float* cov0    = (const float*)d_in[6];
    const int*   y_idx   = (const int*)d_in[7];
    const float* W_ih    = (const float*)d_in[8];
    const float* W_hh    = (const float*)d_in[9];
    const float* b_ih    = (const float*)d_in[10];
    const float* b_hh    = (const float*)d_in[11];
    const float* Wx      = (const float*)d_in[12];
    const float* Ux      = (const float*)d_in[13];
    const float* bx      = (const float*)d_in[14];
    const float* Wc_att  = (const float*)d_in[15];
    const float* b_att   = (const float*)d_in[16];
    const float* W_comb  = (const float*)d_in[17];
    const float* U_att   = (const float*)d_in[18];
    const float* W_cov   = (const float*)d_in[19];
    const float* Wp      = (const float*)d_in[20];
    const float* bp      = (const float*)d_in[21];
    float* out = (float*)d_out;

    void *p_pctx, *p_feats, *p_logits;
    cudaGetSymbolAddress(&p_pctx, g_pctx);
    cudaGetSymbolAddress(&p_feats, g_feats);
    cudaGetSymbolAddress(&p_logits, g_logits);

    init_kernel<<<1, 256>>>(h0, c0, cov0);

    // pctx = context @ Wc_att^T + b_att : M=2560, N=512, K=512
    {
        dim3 grid((TX * BB) / BMg, CC / BNg);   // (20, 4)
        gemm_abT_bias<<<grid, 256>>>(context, Wc_att, b_att, (float*)p_pctx,
                                     TX * BB, CC, CC);
    }

    decoder_kernel<<<NBLK, NTHR>>>(y_emb, context, x_mask, y_mask,
                                   W_ih, W_hh, b_ih, b_hh, Wx, Ux, bx,
                                   W_comb, U_att, W_cov);

    // logits = feats @ Wp^T + bp : M=640, N=30000, K=896
    {
        dim3 grid((TY * BB) / BMg, (VV + BNg - 1) / BNg);   // (5, 235)
        gemm_abT_bias<<<grid, 256>>>((const float*)p_feats, Wp, bp, (float*)p_logits,
                                     TY * BB, VV, FF);
    }

    softmax_cost_kernel<<<TY * BB, 256>>>(y_idx, out);
    finalize_kernel<<<1, 32>>>(y_mask, out);
}

// round 7
// speedup vs baseline: 3.0508x; 1.0673x over previous
#include <cuda_runtime.h>
#include <math.h>

#define TX 160
#define TY 40
#define BB 16
#define HH 256
#define CC 512
#define INDIM 128
#define VV 30000
#define G4 1024      // 4*H
#define FF 896       // H + C + IN

#define NBLK 128
#define NTHR 320

// ---------------- device scratch (static, no allocs) ----------------
__device__ __align__(256) float g_pctx[TX * BB * CC];          // 5.24 MB
__device__ __align__(256) float g_gates[BB * G4];
__device__ __align__(256) float g_hq[BB * CC];
__device__ __align__(256) float g_acc[BB * TX];                // [b][x]
__device__ __align__(256) float g_sc[BB * TX];                 // [b][x]
__device__ __align__(256) float g_atted[BB * CC];
__device__ __align__(256) float g_ifoc[BB * G4];
__device__ __align__(256) float g_feats[TY * BB * FF];         // 2.29 MB
__device__ __align__(256) float g_logits[TY * BB * VV];        // 76.8 MB
__device__ __align__(256) float g_cost[TY * BB];
__device__ float g_cov_sum;
__device__ __align__(128) unsigned g_bar;

// ---------------- helpers ----------------
__device__ __forceinline__ float tanh_fast(float x) {
    float y;
    asm("tanh.approx.f32 %0, %1;" : "=f"(y) : "f"(x));
    return y;
}
__device__ __forceinline__ float sig_fast(float x) {
    return fmaf(tanh_fast(0.5f * x), 0.5f, 0.5f);
}
__device__ __forceinline__ float warp_sum(float s) {
#pragma unroll
    for (int o = 16; o > 0; o >>= 1) s += __shfl_xor_sync(0xffffffffu, s, o);
    return s;
}

__device__ __forceinline__ unsigned long long dup2(float a) {
    unsigned long long r;
    asm("mov.b64 %0, {%1, %1};" : "=l"(r) : "f"(a));
    return r;
}
__device__ __forceinline__ void ffma2(unsigned long long& d, unsigned long long a, unsigned long long b) {
    asm("fma.rn.f32x2 %0, %1, %2, %0;" : "+l"(d) : "l"(a), "l"(b));
}
__device__ __forceinline__ void unpack2(unsigned long long v, float& lo, float& hi) {
    asm("mov.b64 {%0, %1}, %2;" : "=f"(lo), "=f"(hi) : "l"(v));
}

// accumulate one 4-wide K chunk of weight row into all 16 batch accumulators
#define ACC_CHUNK(WPTR, XEXPR) { \
    float4 w = *(const float4*)(WPTR); \
    _Pragma("unroll") \
    for (int b = 0; b < 16; b++) { \
        float4 x = *(const float4*)(XEXPR); \
        acc[b] = fmaf(w.x, x.x, fmaf(w.y, x.y, fmaf(w.z, x.z, fmaf(w.w, x.w, acc[b])))); \
    } }

#define ALLRED16() { \
    _Pragma("unroll") \
    for (int o = 16; o > 0; o >>= 1) { \
        _Pragma("unroll") \
        for (int b = 0; b < 16; b++) acc[b] += __shfl_xor_sync(0xffffffffu, acc[b], o); \
    } }

// fast monotonic grid barrier: no-return red arrival + polite acquire poll
__device__ __forceinline__ void grid_sync(unsigned& epoch) {
    __syncthreads();
    if (threadIdx.x == 0) {
        epoch += gridDim.x;
        asm volatile("red.release.gpu.global.add.u32 [%0], 1;" :: "l"(&g_bar) : "memory");
        unsigned v;
        while (true) {
            asm volatile("ld.acquire.gpu.global.u32 %0, [%1];" : "=r"(v) : "l"(&g_bar) : "memory");
            if (v >= epoch) break;
            __nanosleep(32);
        }
    }
    __syncthreads();
}

// ---------------- init ----------------
__global__ void init_kernel(const float* __restrict__ cov0) {
    int tid = threadIdx.x;
    if (tid == 0) { g_bar = 0u; g_cov_sum = 0.f; }
    for (int i = tid; i < BB * TX; i += blockDim.x) { g_acc[i] = cov0[i]; }
}

// ---------------- GEMM: C = A @ B^T + bias (round-4 version) ----------------
#define BMg 128
#define BNg 128
#define BKg 16
#define TSTR 132

__global__ __launch_bounds__(256, 2) void gemm_abT_bias(
    const float* __restrict__ A, const float* __restrict__ Bm,
    const float* __restrict__ bias, float* __restrict__ Cout,
    int M, int N, int K)
{
    __shared__ __align__(16) float As[BKg * TSTR];
    __shared__ __align__(16) float Bs[BKg * TSTR];

    const int tid = threadIdx.x;
    const int tx = tid & 15;
    const int ty = tid >> 4;
    const int m0 = blockIdx.x * BMg;
    const int n0 = blockIdx.y * BNg;

    unsigned long long acc[8][4];
#pragma unroll
    for (int i = 0; i < 8; i++)
#pragma unroll
        for (int j = 0; j < 4; j++) acc[i][j] = 0ull;

    for (int k0 = 0; k0 < K; k0 += BKg) {
#pragma unroll
        for (int i = 0; i < 2; i++) {
            int f = tid + i * 256;
            int row = f >> 2;
            int kq = f & 3;
            float4 av = *(const float4*)(A + (size_t)(m0 + row) * K + k0 + kq * 4);
            As[(kq * 4 + 0) * TSTR + row] = av.x;
            As[(kq * 4 + 1) * TSTR + row] = av.y;
            As[(kq * 4 + 2) * TSTR + row] = av.z;
            As[(kq * 4 + 3) * TSTR + row] = av.w;
            int gn = n0 + row;
            float4 bv = make_float4(0.f, 0.f, 0.f, 0.f);
            if (gn < N) bv = *(const float4*)(Bm + (size_t)gn * K + k0 + kq * 4);
            Bs[(kq * 4 + 0) * TSTR + row] = bv.x;
            Bs[(kq * 4 + 1) * TSTR + row] = bv.y;
            Bs[(kq * 4 + 2) * TSTR + row] = bv.z;
            Bs[(kq * 4 + 3) * TSTR + row] = bv.w;
        }
        __syncthreads();
#pragma unroll
        for (int k = 0; k < BKg; k++) {
            float4 a0 = *(const float4*)&As[k * TSTR + ty * 4];
            float4 a1 = *(const float4*)&As[k * TSTR + ty * 4 + 64];
            ulonglong2 b0q = *(const ulonglong2*)&Bs[k * TSTR + tx * 4];
            ulonglong2 b1q = *(const ulonglong2*)&Bs[k * TSTR + tx * 4 + 64];
            unsigned long long b0 = b0q.x, b1 = b0q.y, b2 = b1q.x, b3 = b1q.y;
            float af[8] = {a0.x, a0.y, a0.z, a0.w, a1.x, a1.y, a1.z, a1.w};
#pragma unroll
            for (int i = 0; i < 8; i++) {
                unsigned long long a2 = dup2(af[i]);
                ffma2(acc[i][0], a2, b0);
                ffma2(acc[i][1], a2, b1);
                ffma2(acc[i][2], a2, b2);
                ffma2(acc[i][3], a2, b3);
            }
        }
        __syncthreads();
    }
#pragma unroll
    for (int i = 0; i < 8; i++) {
        int m = m0 + ((i < 4) ? (ty * 4 + i) : (64 + ty * 4 + i - 4));
#pragma unroll
        for (int j = 0; j < 4; j++) {
            int n = n0 + ((j < 2) ? (tx * 4 + j * 2) : (64 + tx * 4 + (j - 2) * 2));
            float lo, hi;
            unpack2(acc[i][j], lo, hi);
            if (n < N)     Cout[(size_t)m * N + n]     = lo + bias[n];
            if (n + 1 < N) Cout[(size_t)m * N + n + 1] = hi + bias[n + 1];
        }
    }
}

// ---------------- persistent recurrence: batch-amortized weight reads ----------------
// smem layout (floats): h 4096 | c 4096 | h1 4096 | c1 4096 | watt 160 | attp 320 | wcov 512 | uatt 512
#define OFF_H    0
#define OFF_C    4096
#define OFF_H1   8192
#define OFF_C1   12288
#define OFF_WATT 16384
#define OFF_ATTP 16544
#define OFF_WCOV 16864
#define OFF_UATT 17376
#define SMEM_FLOATS 17888
#define SMEM_BYTES (SMEM_FLOATS * 4)

__global__ __launch_bounds__(NTHR, 1) void decoder_kernel(
    const float* __restrict__ y_emb, const float* __restrict__ context,
    const float* __restrict__ x_mask, const float* __restrict__ y_mask,
    const float* __restrict__ h0, const float* __restrict__ c0,
    const float* __restrict__ W_ih, const float* __restrict__ W_hh,
    const float* __restrict__ b_ih, const float* __restrict__ b_hh,
    const float* __restrict__ Wx, const float* __restrict__ Ux, const float* __restrict__ bx,
    const float* __restrict__ W_comb, const float* __restrict__ U_att,
    const float* __restrict__ W_cov)
{
    extern __shared__ __align__(16) float sh[];
    float* sh_h    = sh + OFF_H;
    float* sh_c    = sh + OFF_C;
    float* sh_h1   = sh + OFF_H1;
    float* sh_c1   = sh + OFF_C1;
    float* sh_watt = sh + OFF_WATT;
    float* sh_attp = sh + OFF_ATTP;
    float* sh_wcov = sh + OFF_WCOV;
    float* sh_uatt = sh + OFF_UATT;

    const int tid = threadIdx.x;
    const int bk = blockIdx.x;
    const int lane = tid & 31;
    const int lwid = tid >> 5;     // 0..9
    const int myb = bk >> 3;       // batch this block serves in P5 (0..15)
    const int sub = bk & 7;        // 0..7 within batch group
    unsigned epoch = 0;

    for (int i = tid; i < BB * HH; i += NTHR) { sh_h[i] = h0[i]; sh_c[i] = c0[i]; }
    for (int i = tid; i < CC; i += NTHR) { sh_wcov[i] = W_cov[i]; sh_uatt[i] = U_att[i]; }
    __syncthreads();

    for (int t = 0; t < TY; t++) {
        const float* yrow = y_emb + (size_t)t * BB * INDIM;

        // ---- P1: gates[b][j] — warp owns row j, all 16 batches ----
        if (lwid < 8) {
            int j = lwid * NBLK + bk;                       // 0..1023
            float acc[16];
#pragma unroll
            for (int b = 0; b < 16; b++) acc[b] = 0.f;
            ACC_CHUNK(W_ih + (size_t)j * INDIM + lane * 4,       yrow + b * INDIM + lane * 4);
            ACC_CHUNK(W_hh + (size_t)j * HH + lane * 4,          sh_h + b * HH + lane * 4);
            ACC_CHUNK(W_hh + (size_t)j * HH + 128 + lane * 4,    sh_h + b * HH + 128 + lane * 4);
            ALLRED16();
            float bias = b_ih[j] + b_hh[j];
#pragma unroll
            for (int b = 0; b < 16; b++)
                if (lane == b) g_gates[b * G4 + j] = acc[b] + bias;
        }
        grid_sync(epoch);

        // ---- P2: LSTM cell 1, block-redundant into smem ----
        for (int idx = tid; idx < BB * HH; idx += NTHR) {
            int b = idx >> 8, u = idx & 255;
            const float* gb = g_gates + b * G4 + u;
            float gi = gb[0], gf = gb[HH], gg = gb[2 * HH], go = gb[3 * HH];
            float c_old = sh_c[idx], h_old = sh_h[idx];
            float c1 = sig_fast(gf) * c_old + sig_fast(gi) * tanh_fast(gg);
            float h1 = sig_fast(go) * tanh_fast(c1);
            float ym = y_mask[t * BB + b];
            sh_h1[idx] = ym * h1 + (1.f - ym) * h_old;
            sh_c1[idx] = ym * c1 + (1.f - ym) * c_old;
        }
        __syncthreads();

        // ---- P3: hq[b][o] — warp owns row o, all 16 batches ----
        if (lwid < 4) {
            int o = lwid * NBLK + bk;                       // 0..511
            const float* wr = W_comb + (size_t)o * (2 * HH);
            float acc[16];
#pragma unroll
            for (int b = 0; b < 16; b++) acc[b] = 0.f;
            ACC_CHUNK(wr + lane * 4,        sh_h1 + b * HH + lane * 4);
            ACC_CHUNK(wr + 128 + lane * 4,  sh_h1 + b * HH + 128 + lane * 4);
            ACC_CHUNK(wr + 256 + lane * 4,  sh_c1 + b * HH + lane * 4);
            ACC_CHUNK(wr + 384 + lane * 4,  sh_c1 + b * HH + 128 + lane * 4);
            ALLRED16();
#pragma unroll
            for (int b = 0; b < 16; b++)
                if (lane == b) g_hq[b * CC + o] = acc[b];
        }
        grid_sync(epoch);

        // ---- P4: attention scores, 20 jobs/block spread evenly ----
#pragma unroll
        for (int r = 0; r < 2; r++) {
            int p = (r * 10 + lwid) * NBLK + bk;            // 0..2559
            int x = p >> 4, b = p & 15;
            float accv = g_acc[b * TX + x];
            const float* pc = g_pctx + (size_t)p * CC;
            const float* hqb = g_hq + b * CC;
            float s = 0.f;
#pragma unroll
            for (int i = 0; i < 16; i++) {
                int c = i * 32 + lane;
                s += tanh_fast(fmaf(accv, sh_wcov[c], pc[c] + hqb[c])) * sh_uatt[c];
            }
            s = warp_sum(s);
            if (lane == 0) g_sc[b * TX + x] = x_mask[p] * s;
        }
        grid_sync(epoch);

        // ---- P5a: softmax for this block's batch (warp 0) ----
        if (lwid == 0) {
            float v[5];
            float mx = -3.4e38f;
#pragma unroll
            for (int i = 0; i < 5; i++) {
                v[i] = g_sc[myb * TX + i * 32 + lane];
                mx = fmaxf(mx, v[i]);
            }
#pragma unroll
            for (int o = 16; o > 0; o >>= 1) mx = fmaxf(mx, __shfl_xor_sync(0xffffffffu, mx, o));
            float sm = 0.f;
#pragma unroll
            for (int i = 0; i < 5; i++) {
                v[i] = __expf(v[i] - mx) * x_mask[(i * 32 + lane) * BB + myb];
                sm += v[i];
            }
            sm = warp_sum(sm);
            float inv = __fdividef(1.f, sm);
#pragma unroll
            for (int i = 0; i < 5; i++) sh_watt[i * 32 + lane] = v[i] * inv;
        }
        __syncthreads();

        // ---- P5b: atted partials — block covers cck {2*sub, 2*sub+1} x 5 x-chunks ----
        {
            int jid = sub * 10 + lwid;                      // 0..79
            int cck = jid / 5, xck = jid % 5;
            int c = cck * 32 + lane;
            float s = 0.f;
#pragma unroll 8
            for (int i = 0; i < 32; i++) {
                int x = xck * 32 + i;
                s = fmaf(sh_watt[x], context[(size_t)(x * BB + myb) * CC + c], s);
            }
            sh_attp[(cck & 1) * 160 + xck * 32 + lane] = s;
        }
        __syncthreads();
        if (tid < 64) {
            int lc = tid >> 5, cl = tid & 31;
            const float* ap = sh_attp + lc * 160 + cl;
            float s = ap[0] + ap[32] + ap[64] + ap[96] + ap[128];
            g_atted[myb * CC + (2 * sub + lc) * 32 + cl] = s;
        }
        // coverage update: one block per batch (sub==0), warp 2 (disjoint from tid<64)
        if (sub == 0 && lwid == 2) {
            float part = 0.f;
#pragma unroll
            for (int i = 0; i < 5; i++) {
                int x = i * 32 + lane;
                float w = sh_watt[x];
                float old = g_acc[myb * TX + x];
                part += fminf(w, old);
                g_acc[myb * TX + x] = old + w;
            }
            part = warp_sum(part);
            if (lane == 0) atomicAdd(&g_cov_sum, part);
        }
        grid_sync(epoch);

        // ---- P6: ifoc[b][j] — warp owns row j, all 16 batches ----
        if (lwid < 8) {
            int j = lwid * NBLK + bk;                       // 0..1023
            float acc[16];
#pragma unroll
            for (int b = 0; b < 16; b++) acc[b] = 0.f;
            ACC_CHUNK(Ux + (size_t)j * HH + lane * 4,        sh_h1 + b * HH + lane * 4);
            ACC_CHUNK(Ux + (size_t)j * HH + 128 + lane * 4,  sh_h1 + b * HH + 128 + lane * 4);
#pragma unroll
            for (int cc = 0; cc < 4; cc++) {
                ACC_CHUNK(Wx + (size_t)j * CC + cc * 128 + lane * 4,
                          g_atted + b * CC + cc * 128 + lane * 4);
            }
            ALLRED16();
            float bias = bx[j];
#pragma unroll
            for (int b = 0; b < 16; b++)
                if (lane == b) g_ifoc[b * G4 + j] = acc[b] + bias;
        }
        grid_sync(epoch);

        // ---- P7: LSTM cell 2 (block-redundant, bitwise-identical) + feats ----
        for (int idx = tid; idx < BB * HH; idx += NTHR) {
            int b = idx >> 8, u = idx & 255;
            const float* fb = g_ifoc + b * G4 + u;
            float i2 = fb[0], f2 = fb[HH], o2 = fb[2 * HH], g2 = fb[3 * HH];
            float c1 = sh_c1[idx], h1 = sh_h1[idx];
            float c2 = sig_fast(f2) * c1 + sig_fast(i2) * tanh_fast(g2);
            float h2 = sig_fast(o2) * tanh_fast(c2);
            float ym = y_mask[t * BB + b];
            c2 = ym * c2 + (1.f - ym) * c1;
            h2 = ym * h2 + (1.f - ym) * h1;
            sh_h[idx] = h2;
            sh_c[idx] = c2;
            g_feats[(size_t)(t * BB + b) * FF + u] = h2;   // redundant, identical values
        }
        // distributed tail: atted + y copy into feats
        for (int idx2 = bk * NTHR + tid; idx2 < BB * (CC + INDIM); idx2 += NBLK * NTHR) {
            if (idx2 < BB * CC) {
                int b = idx2 >> 9, c = idx2 & 511;
                g_feats[(size_t)(t * BB + b) * FF + HH + c] = g_atted[idx2];
            } else {
                int q = idx2 - BB * CC;
                int b = q >> 7, kk = q & 127;
                g_feats[(size_t)(t * BB + b) * FF + HH + CC + kk] = yrow[b * INDIM + kk];
            }
        }
        __syncthreads();   // sh_h/sh_c ready for next step's P1/P2
    }
}

// ---------------- online softmax / cost per row ----------------
__global__ __launch_bounds__(256) void softmax_cost_kernel(const int* __restrict__ y_idx,
                                                           float* __restrict__ out) {
    __shared__ float smx[256], ssm[256];
    const int m = blockIdx.x;
    const int tid = threadIdx.x;
    const float* row = g_logits + (size_t)m * VV;

    float mx = -3.4e38f, sm = 0.f;
    for (int v = tid; v < VV; v += 256) {
        float x = row[v];
        float nm = fmaxf(mx, x);
        sm = sm * __expf(mx - nm) + __expf(x - nm);
        mx = nm;
    }
    smx[tid] = mx; ssm[tid] = sm; __syncthreads();
    for (int s = 128; s > 0; s >>= 1) {
        if (tid < s) {
            float m2 = smx[tid + s], s2 = ssm[tid + s];
            float nm = fmaxf(smx[tid], m2);
            ssm[tid] = ssm[tid] * __expf(smx[tid] - nm) + s2 * __expf(m2 - nm);
            smx[tid] = nm;
        }
        __syncthreads();
    }
    float M = smx[0], S = ssm[0];
    if (tid == 0) g_cost[m] = M + logf(S) - row[y_idx[m]];

    if (m >= (TY - 1) * BB) {
        int b = m - (TY - 1) * BB;
        float inv = __fdividef(1.f, S);
        for (int v = tid; v < VV; v += 256)
            out[(size_t)b * VV + v] = __expf(row[v] - M) * inv;
    }
}

// ---------------- final scalars ----------------
__global__ void finalize_kernel(const float* __restrict__ y_mask, float* __restrict__ out) {
    int b = threadIdx.x;
    float cb = 0.f;
    if (b < BB) {
        float num = 0.f, den = 0.f;
        for (int t = 0; t < TY; t++) {
            float ym = y_mask[t * BB + b];
            num += g_cost[t * BB + b] * ym;
            den += ym;
        }
        cb = num / den;
    }
#pragma unroll
    for (int o = 16; o > 0; o >>= 1) cb += __shfl_xor_sync(0xffffffffu, cb, o);
    if (threadIdx.x == 0) {
        out[(size_t)BB * VV]     = cb / (float)BB;
        out[(size_t)BB * VV + 1] = g_cov_sum / (float)(TY * BB);
    }
}

// ---------------- launch ----------------
extern "C" void kernel_launch(void* const* d_in, const int* in_sizes, int n_in,
                              void* d_out, int out_size) {
    const float* y_emb   = (const float*)d_in[0];
    const float* context = (const float*)d_in[1];
    const float* h0      = (const float*)d_in[2];
    const float* c0      = (const float*)d_in[3];
    const float* x_mask  = (const float*)d_in[4];
    const float* y_mask  = (const float*)d_in[5];
    const float* cov0    = (const float*)d_in[6];
    const int*   y_idx   = (const int*)d_in[7];
    const float* W_ih    = (const float*)d_in[8];
    const float* W_hh    = (const float*)d_in[9];
    const float* b_ih    = (const float*)d_in[10];
    const float* b_hh    = (const float*)d_in[11];
    const float* Wx      = (const float*)d_in[12];
    const float* Ux      = (const float*)d_in[13];
    const float* bx      = (const float*)d_in[14];
    const float* Wc_att  = (const float*)d_in[15];
    const float* b_att   = (const float*)d_in[16];
    const float* W_comb  = (const float*)d_in[17];
    const float* U_att   = (const float*)d_in[18];
    const float* W_cov   = (const float*)d_in[19];
    const float* Wp      = (const float*)d_in[20];
    const float* bp      = (const float*)d_in[21];
    float* out = (float*)d_out;

    void *p_pctx, *p_feats, *p_logits;
    cudaGetSymbolAddress(&p_pctx, g_pctx);
    cudaGetSymbolAddress(&p_feats, g_feats);
    cudaGetSymbolAddress(&p_logits, g_logits);

    cudaFuncSetAttribute(decoder_kernel,
                         cudaFuncAttributeMaxDynamicSharedMemorySize, SMEM_BYTES);

    init_kernel<<<1, 256>>>(cov0);

    // pctx = context @ Wc_att^T + b_att : M=2560, N=512, K=512
    {
        dim3 grid((TX * BB) / BMg, CC / BNg);   // (20, 4)
        gemm_abT_bias<<<grid, 256>>>(context, Wc_att, b_att, (float*)p_pctx,
                                     TX * BB, CC, CC);
    }

    decoder_kernel<<<NBLK, NTHR, SMEM_BYTES>>>(y_emb, context, x_mask, y_mask,
                                               h0, c0,
                                               W_ih, W_hh, b_ih, b_hh, Wx, Ux, bx,
                                               W_comb, U_att, W_cov);

    // logits = feats @ Wp^T + bp : M=640, N=30000, K=896
    {
        dim3 grid((TY * BB) / BMg, (VV + BNg - 1) / BNg);   // (5, 235)
        gemm_abT_bias<<<grid, 256>>>((const float*)p_feats, Wp, bp, (float*)p_logits,
                                     TY * BB, VV, FF);
    }

    softmax_cost_kernel<<<TY * BB, 256>>>(y_idx, out);
    finalize_kernel<<<1, 32>>>(y_mask, out);
}